// round 12
// baseline (speedup 1.0000x reference)
#include <cuda_runtime.h>
#include <cuda_fp16.h>
#include <math.h>
#include <stdint.h>

#define NB    8
#define NPTS  4096
#define BN    32768
#define NEDGE 524288
#define C0    64
#define C1    128
#define C2    512

// ---------------- scratch ----------------
__device__ __half g_h0[BN * C0];     // hs0 = dinv*h0, fp16 payload
__device__ float  g_agg0[BN * C0];   // gather output, f32
__device__ __half g_h1[BN * C1];
__device__ float  g_agg1[BN * C1];
__device__ int    g_cnt[BN];
__device__ int    g_rowstart[BN + 1];
__device__ int    g_cur[BN];
__device__ int    g_el[NEDGE];
__device__ float  g_dinv[BN];
__device__ float  g_lat[NB * C2];
__device__ float  g_lat2[NB * C2];
__device__ float  g_base[NB * 6];

__device__ __forceinline__ float selu_f(float v) {
    const float scale = 1.0507009873554805f;
    const float alpha = 1.6732632423543772f;
    return v > 0.0f ? scale * v : scale * alpha * expm1f(v);
}

__device__ __forceinline__ void atomicMaxF(float* addr, float v) {
    if (v >= 0.0f) atomicMax((int*)addr, __float_as_int(v));
    else           atomicMin((unsigned int*)addr, __float_as_uint(v));
}

__device__ __forceinline__ float f2tf32f(float v) {
    uint32_t r;
    asm("cvt.rna.tf32.f32 %0, %1;" : "=r"(r) : "f"(v));
    return __uint_as_float(r);
}

__device__ __forceinline__ uint32_t h2_bits(__half2 h) {
    uint32_t u;
    *reinterpret_cast<__half2*>(&u) = h;
    return u;
}
__device__ __forceinline__ __half2 bits_h2(uint32_t u) {
    return *reinterpret_cast<__half2*>(&u);
}

__device__ __forceinline__ uint4 ldg_nc_u4(const uint4* p) {
    uint4 v;
    asm volatile("ld.global.nc.v4.u32 {%0,%1,%2,%3}, [%4];"
                 : "=r"(v.x), "=r"(v.y), "=r"(v.z), "=r"(v.w) : "l"(p));
    return v;
}

__device__ __forceinline__ void mma_tf32(float d[4],
                                         uint32_t a0, uint32_t a1, uint32_t a2, uint32_t a3,
                                         uint32_t b0, uint32_t b1) {
    asm volatile("mma.sync.aligned.m16n8k8.row.col.f32.tf32.tf32.f32 "
                 "{%0,%1,%2,%3},{%4,%5,%6,%7},{%8,%9},{%0,%1,%2,%3};"
                 : "+f"(d[0]), "+f"(d[1]), "+f"(d[2]), "+f"(d[3])
                 : "r"(a0), "r"(a1), "r"(a2), "r"(a3), "r"(b0), "r"(b1));
}

// ---------------- init / degree ----------------
__global__ void init_kernel() {
    int i = blockIdx.x * blockDim.x + threadIdx.x;
    if (i < BN) g_cnt[i] = 0;
    if (i < NB * C2) g_lat[i] = __int_as_float(0xff800000);
}
__global__ void cnt_kernel(const int* __restrict__ dst) {
    int e = blockIdx.x * blockDim.x + threadIdx.x;
    if (e < NEDGE) atomicAdd(&g_cnt[dst[e]], 1);
}

// ---------------- single-block scan: rowstart/cursor/dinv ----------------
__global__ void __launch_bounds__(1024) scan_kernel() {
    __shared__ int ssum[1024];
    int t = threadIdx.x;
    int base = t << 5;
    int local[32];
    int s = 0;
    #pragma unroll
    for (int j = 0; j < 32; j++) { local[j] = g_cnt[base + j]; s += local[j]; }
    ssum[t] = s;
    __syncthreads();
    for (int off = 1; off < 1024; off <<= 1) {
        int v = (t >= off) ? ssum[t - off] : 0;
        __syncthreads();
        ssum[t] += v;
        __syncthreads();
    }
    int run = ssum[t] - s;
    #pragma unroll
    for (int j = 0; j < 32; j++) {
        g_rowstart[base + j] = run;
        g_cur[base + j] = run;
        g_dinv[base + j] = rsqrtf((float)(local[j] + 1));   // +1 self loop
        run += local[j];
    }
    if (t == 1023) g_rowstart[BN] = run;
}

// ---------------- CSR fill ----------------
__global__ void fill_kernel(const int* __restrict__ src, const int* __restrict__ dst) {
    int e = blockIdx.x * blockDim.x + threadIdx.x;
    if (e >= NEDGE) return;
    int d = dst[e];
    int pos = atomicAdd(&g_cur[d], 1);
    g_el[pos] = src[e];
}

// ---------------- cov + 12->64 + selu -> hs0 fp16 ----------------
// 128 threads, 32 points per block (R7/R11 shape).
__global__ void __launch_bounds__(128)
cov_e1_kernel(const float* __restrict__ x,
              const float* __restrict__ w_e1,
              const float* __restrict__ b_e1) {
    __shared__ float xw[56][3];
    __shared__ float ws[12 * 64];
    __shared__ float bs[64];
    __shared__ float feat_s[32][13];
    __shared__ float out_s[32][68];
    int t = threadIdx.x;
    int blk = blockIdx.x;
    int b = blk >> 7;
    int n_base = (blk & 127) << 5;
    int point0 = blk << 5;

    if (t < 56) {
        int idx = n_base + t - 12;
        idx = min(max(idx, 0), NPTS - 1);
        const float* xp = x + (((size_t)b << 12) + idx) * 3;
        xw[t][0] = xp[0]; xw[t][1] = xp[1]; xw[t][2] = xp[2];
    }
    for (int i = t; i < 12 * 64; i += 128) ws[i] = w_e1[i];
    if (t < 64) bs[t] = b_e1[t];
    __syncthreads();

    if (t < 32) {
        int n = n_base + t;
        float m0 = 0.f, m1 = 0.f, m2 = 0.f, cnt = 0.f;
        #pragma unroll
        for (int w = 0; w < 25; w++) {
            int nn = n + w - 12;
            if (nn >= 0 && nn < NPTS) {
                m0 += xw[t + w][0]; m1 += xw[t + w][1]; m2 += xw[t + w][2];
                cnt += 1.0f;
            }
        }
        float ic = 1.0f / cnt;
        m0 *= ic; m1 *= ic; m2 *= ic;
        float c00=0,c01=0,c02=0,c11=0,c12=0,c22=0;
        #pragma unroll
        for (int w = 0; w < 25; w++) {
            int nn = n + w - 12;
            if (nn >= 0 && nn < NPTS) {
                float d0 = xw[t + w][0] - m0;
                float d1 = xw[t + w][1] - m1;
                float d2 = xw[t + w][2] - m2;
                c00 = fmaf(d0,d0,c00); c01 = fmaf(d0,d1,c01); c02 = fmaf(d0,d2,c02);
                c11 = fmaf(d1,d1,c11); c12 = fmaf(d1,d2,c12); c22 = fmaf(d2,d2,c22);
            }
        }
        const float s = 1.0f / 23.0f;
        feat_s[t][0] = xw[t + 12][0]; feat_s[t][1] = xw[t + 12][1]; feat_s[t][2] = xw[t + 12][2];
        feat_s[t][3] = c00 * s; feat_s[t][4]  = c01 * s; feat_s[t][5]  = c02 * s;
        feat_s[t][6] = c01 * s; feat_s[t][7]  = c11 * s; feat_s[t][8]  = c12 * s;
        feat_s[t][9] = c02 * s; feat_s[t][10] = c12 * s; feat_s[t][11] = c22 * s;
    }
    __syncthreads();

    int pt = t >> 2, quarter = t & 3;
    float dv = g_dinv[point0 + pt];
    float feat[12];
    #pragma unroll
    for (int k = 0; k < 12; k++) feat[k] = feat_s[pt][k];
    #pragma unroll
    for (int jj = 0; jj < 16; jj++) {
        int j = (quarter << 4) + jj;
        float acc = bs[j];
        #pragma unroll
        for (int k = 0; k < 12; k++) acc = fmaf(feat[k], ws[k * 64 + j], acc);
        out_s[pt][j] = dv * selu_f(acc);
    }
    __syncthreads();

    // write fp16 h0 only (gather computes the self term)
    for (int i = t; i < 256; i += 128) {
        int row = i >> 3, seg = i & 7;
        const float* src = &out_s[row][seg << 3];
        uint4 pk;
        pk.x = h2_bits(__floats2half2_rn(src[0], src[1]));
        pk.y = h2_bits(__floats2half2_rn(src[2], src[3]));
        pk.z = h2_bits(__floats2half2_rn(src[4], src[5]));
        pk.w = h2_bits(__floats2half2_rn(src[6], src[7]));
        *reinterpret_cast<uint4*>(g_h0 + (size_t)(point0 + row) * 64 + (seg << 3)) = pk;
    }
}

// ---------------- CSR gather: agg[n] = hs[n] + sum hs[el], f32 accumulation ----------------
// LOGS = log2(uint4 chunks per row); row halves = 8<<LOGS. (1<<LOGS) lanes per node.
template<int LOGS>
__global__ void __launch_bounds__(256)
gather_kernel(const __half* __restrict__ hs, float* __restrict__ agg) {
    int idx = blockIdx.x * 256 + threadIdx.x;
    int node = idx >> LOGS;
    int slot = idx & ((1 << LOGS) - 1);
    int rs = g_rowstart[node], re = g_rowstart[node + 1];
    const uint4* rowp = reinterpret_cast<const uint4*>(hs);

    float acc[8];
    {
        uint4 v = ldg_nc_u4(rowp + ((size_t)node << LOGS) + slot);
        uint32_t w[4] = {v.x, v.y, v.z, v.w};
        #pragma unroll
        for (int j = 0; j < 4; j++) {
            float2 f = __half22float2(bits_h2(w[j]));
            acc[2 * j] = f.x; acc[2 * j + 1] = f.y;
        }
    }

    int e = rs;
    for (; e + 4 <= re; e += 4) {
        int id[4];
        #pragma unroll
        for (int j = 0; j < 4; j++) id[j] = __ldg(g_el + e + j);
        uint4 v[4];
        #pragma unroll
        for (int j = 0; j < 4; j++) v[j] = ldg_nc_u4(rowp + (((size_t)id[j]) << LOGS) + slot);
        #pragma unroll
        for (int j = 0; j < 4; j++) {
            uint32_t w[4] = {v[j].x, v[j].y, v[j].z, v[j].w};
            #pragma unroll
            for (int q = 0; q < 4; q++) {
                float2 f = __half22float2(bits_h2(w[q]));
                acc[2 * q] += f.x; acc[2 * q + 1] += f.y;
            }
        }
    }
    for (; e < re; e++) {
        int s = __ldg(g_el + e);
        uint4 v = ldg_nc_u4(rowp + (((size_t)s) << LOGS) + slot);
        uint32_t w[4] = {v.x, v.y, v.z, v.w};
        #pragma unroll
        for (int q = 0; q < 4; q++) {
            float2 f = __half22float2(bits_h2(w[q]));
            acc[2 * q] += f.x; acc[2 * q + 1] += f.y;
        }
    }

    size_t off = ((size_t)node << (LOGS + 3)) + (slot << 3);
    float4 lo = make_float4(acc[0], acc[1], acc[2], acc[3]);
    float4 hi = make_float4(acc[4], acc[5], acc[6], acc[7]);
    *reinterpret_cast<float4*>(agg + off)     = lo;
    *reinterpret_cast<float4*>(agg + off + 4) = hi;
}

// ---------------- single-pass TF32 GEMM, f32 A operand, 128x128 tile, double-buffered ----------------
// out = selu( (dinv[row]*A[row]) @ W + bias ); !DO_MAX writes fp16 to O1; DO_MAX -> lat f32.
template<int N, int K, bool DO_MAX>
__global__ void __launch_bounds__(256, 2)
gemm_tf32_kernel(const float* __restrict__ A, const float* __restrict__ dinv,
                 const float* __restrict__ Wt, const float* __restrict__ bias,
                 __half* __restrict__ O1, float* __restrict__ lat) {
    __shared__ float Ah[2][128][20];
    __shared__ float Bh[2][16][132];

    int tid = threadIdx.x;
    int warp = tid >> 5, lane = tid & 31;
    int wm = warp >> 2, wn = warp & 3;
    int g = lane >> 2, c = lane & 3;
    int row0 = blockIdx.y * 128, col0 = blockIdx.x * 128;

    int ar = tid >> 1;
    int ak = (tid & 1) << 3;
    float dv = dinv[row0 + ar];
    int bkr = tid >> 4;
    int bc0 = (tid & 15) << 3;

    const int KT = K / 16;

    float d[4][4][4];
    #pragma unroll
    for (int mt = 0; mt < 4; mt++)
        #pragma unroll
        for (int nt = 0; nt < 4; nt++)
            #pragma unroll
            for (int r = 0; r < 4; r++) d[mt][nt][r] = 0.0f;

    auto stage_a = [&](int buf, float4 a0, float4 a1) {
        Ah[buf][ar][ak + 0] = f2tf32f(dv * a0.x); Ah[buf][ar][ak + 1] = f2tf32f(dv * a0.y);
        Ah[buf][ar][ak + 2] = f2tf32f(dv * a0.z); Ah[buf][ar][ak + 3] = f2tf32f(dv * a0.w);
        Ah[buf][ar][ak + 4] = f2tf32f(dv * a1.x); Ah[buf][ar][ak + 5] = f2tf32f(dv * a1.y);
        Ah[buf][ar][ak + 6] = f2tf32f(dv * a1.z); Ah[buf][ar][ak + 7] = f2tf32f(dv * a1.w);
    };
    auto stage_b = [&](int buf, float4 b0, float4 b1) {
        Bh[buf][bkr][bc0 + 0] = f2tf32f(b0.x); Bh[buf][bkr][bc0 + 1] = f2tf32f(b0.y);
        Bh[buf][bkr][bc0 + 2] = f2tf32f(b0.z); Bh[buf][bkr][bc0 + 3] = f2tf32f(b0.w);
        Bh[buf][bkr][bc0 + 4] = f2tf32f(b1.x); Bh[buf][bkr][bc0 + 5] = f2tf32f(b1.y);
        Bh[buf][bkr][bc0 + 6] = f2tf32f(b1.z); Bh[buf][bkr][bc0 + 7] = f2tf32f(b1.w);
    };

    {
        float4 a0 = *reinterpret_cast<const float4*>(A + (size_t)(row0 + ar) * K + ak);
        float4 a1 = *reinterpret_cast<const float4*>(A + (size_t)(row0 + ar) * K + ak + 4);
        stage_a(0, a0, a1);
        float4 b0 = *reinterpret_cast<const float4*>(Wt + (size_t)bkr * N + col0 + bc0);
        float4 b1 = *reinterpret_cast<const float4*>(Wt + (size_t)bkr * N + col0 + bc0 + 4);
        stage_b(0, b0, b1);
    }
    __syncthreads();

    for (int kt = 0; kt < KT; kt++) {
        int cur = kt & 1, nxt = cur ^ 1;
        float4 a0, a1, b0, b1;
        bool more = (kt + 1 < KT);
        if (more) {
            int koff = (kt + 1) * 16;
            a0 = *reinterpret_cast<const float4*>(A + (size_t)(row0 + ar) * K + koff + ak);
            a1 = *reinterpret_cast<const float4*>(A + (size_t)(row0 + ar) * K + koff + ak + 4);
            b0 = *reinterpret_cast<const float4*>(Wt + (size_t)(koff + bkr) * N + col0 + bc0);
            b1 = *reinterpret_cast<const float4*>(Wt + (size_t)(koff + bkr) * N + col0 + bc0 + 4);
        }

        #pragma unroll
        for (int ks = 0; ks < 2; ks++) {
            int k0 = ks << 3;
            uint32_t af[4][4];
            #pragma unroll
            for (int mt = 0; mt < 4; mt++) {
                int rm = wm * 64 + mt * 16;
                af[mt][0] = __float_as_uint(Ah[cur][rm + g][k0 + c]);
                af[mt][1] = __float_as_uint(Ah[cur][rm + g + 8][k0 + c]);
                af[mt][2] = __float_as_uint(Ah[cur][rm + g][k0 + c + 4]);
                af[mt][3] = __float_as_uint(Ah[cur][rm + g + 8][k0 + c + 4]);
            }
            uint32_t bf[4][2];
            #pragma unroll
            for (int nt = 0; nt < 4; nt++) {
                int nb = wn * 32 + nt * 8;
                bf[nt][0] = __float_as_uint(Bh[cur][k0 + c][nb + g]);
                bf[nt][1] = __float_as_uint(Bh[cur][k0 + c + 4][nb + g]);
            }
            #pragma unroll
            for (int mt = 0; mt < 4; mt++)
                #pragma unroll
                for (int nt = 0; nt < 4; nt++)
                    mma_tf32(d[mt][nt], af[mt][0], af[mt][1], af[mt][2], af[mt][3],
                             bf[nt][0], bf[nt][1]);
        }

        if (more) { stage_a(nxt, a0, a1); stage_b(nxt, b0, b1); }
        __syncthreads();
    }

    float bv[4][2];
    #pragma unroll
    for (int nt = 0; nt < 4; nt++) {
        int cc = col0 + wn * 32 + nt * 8 + (c << 1);
        bv[nt][0] = bias[cc];
        bv[nt][1] = bias[cc + 1];
    }

    if (!DO_MAX) {
        #pragma unroll
        for (int mt = 0; mt < 4; mt++) {
            int rbase = row0 + wm * 64 + mt * 16;
            #pragma unroll
            for (int half = 0; half < 2; half++) {
                int r = rbase + g + half * 8;
                float dv2 = dinv[r];
                #pragma unroll
                for (int nt = 0; nt < 4; nt++) {
                    int cc = col0 + wn * 32 + nt * 8 + (c << 1);
                    __half2 o = __floats2half2_rn(
                        dv2 * selu_f(d[mt][nt][half * 2 + 0] + bv[nt][0]),
                        dv2 * selu_f(d[mt][nt][half * 2 + 1] + bv[nt][1]));
                    *reinterpret_cast<__half2*>(O1 + (size_t)r * N + cc) = o;
                }
            }
        }
    } else {
        float mv[4][2];
        #pragma unroll
        for (int nt = 0; nt < 4; nt++) { mv[nt][0] = mv[nt][1] = __int_as_float(0xff800000); }
        #pragma unroll
        for (int mt = 0; mt < 4; mt++)
            #pragma unroll
            for (int nt = 0; nt < 4; nt++) {
                mv[nt][0] = fmaxf(mv[nt][0], fmaxf(selu_f(d[mt][nt][0] + bv[nt][0]),
                                                   selu_f(d[mt][nt][2] + bv[nt][0])));
                mv[nt][1] = fmaxf(mv[nt][1], fmaxf(selu_f(d[mt][nt][1] + bv[nt][1]),
                                                   selu_f(d[mt][nt][3] + bv[nt][1])));
            }
        #pragma unroll
        for (int off = 4; off <= 16; off <<= 1)
            #pragma unroll
            for (int nt = 0; nt < 4; nt++) {
                mv[nt][0] = fmaxf(mv[nt][0], __shfl_xor_sync(0xffffffffu, mv[nt][0], off));
                mv[nt][1] = fmaxf(mv[nt][1], __shfl_xor_sync(0xffffffffu, mv[nt][1], off));
            }
        if (lane < 4) {
            int b = row0 >> 12;
            #pragma unroll
            for (int nt = 0; nt < 4; nt++) {
                int cc = col0 + wn * 32 + nt * 8 + (lane << 1);
                atomicMaxF(&lat[b * C2 + cc], mv[nt][0]);
                atomicMaxF(&lat[b * C2 + cc + 1], mv[nt][1]);
            }
        }
    }
}

// ---------------- lat2 = selu(lat @ w_e2 + b_e2) ----------------
__global__ void e2_kernel(const float* __restrict__ lat, const float* __restrict__ w,
                          const float* __restrict__ bias, float* __restrict__ lat2) {
    __shared__ float row[C2];
    int c = threadIdx.x;
    row[c] = lat[blockIdx.x * C2 + c];
    __syncthreads();
    float acc = bias[c];
    #pragma unroll 8
    for (int k = 0; k < C2; k++) acc = fmaf(row[k], w[k * C2 + c], acc);
    lat2[blockIdx.x * C2 + c] = selu_f(acc);
}

// ---------------- decoder ----------------
__global__ void base_kernel(const float* __restrict__ lat2,
                            const float* __restrict__ w_d1,
                            const float* __restrict__ w_d2,
                            float* __restrict__ base) {
    int o = blockIdx.x;
    int b = o / 6, t = o % 6, j = t % 3;
    const float* w = (t < 3) ? w_d1 : w_d2;
    int lane = threadIdx.x;
    float s = 0.0f;
    for (int c = lane; c < C2; c += 32) s += lat2[b * C2 + c] * w[c * 3 + j];
    #pragma unroll
    for (int off = 16; off > 0; off >>= 1) s += __shfl_xor_sync(0xffffffffu, s, off);
    if (lane == 0) base[b * 6 + t] = s;
}

__global__ void final_kernel(const float* __restrict__ base,
                             const float* __restrict__ w_d1, const float* __restrict__ b_d1,
                             const float* __restrict__ w_d2, const float* __restrict__ b_d2,
                             float* __restrict__ out) {
    int idx = blockIdx.x * blockDim.x + threadIdx.x;
    int b = idx >> 12, n = idx & 4095;
    int ix = n / 46, iy = n % 46;
    float y0 = 1.0f + ix * (119.0f / 90.0f);
    float y1 = 1.0f + iy * (59.0f / 45.0f);
    float kk[3];
    #pragma unroll
    for (int j = 0; j < 3; j++)
        kk[j] = selu_f(base[b * 6 + j] + y0 * w_d1[512 * 3 + j] + y1 * w_d1[513 * 3 + j] + b_d1[j]);
    #pragma unroll
    for (int j = 0; j < 3; j++) {
        float v = base[b * 6 + 3 + j]
                + kk[0] * w_d2[512 * 3 + j]
                + kk[1] * w_d2[513 * 3 + j]
                + kk[2] * w_d2[514 * 3 + j]
                + b_d2[j];
        out[(size_t)idx * 3 + j] = selu_f(v);
    }
}

// ---------------- launch ----------------
extern "C" void kernel_launch(void* const* d_in, const int* in_sizes, int n_in,
                              void* d_out, int out_size) {
    const float* x    = (const float*)d_in[0];
    const int*   knn  = (const int*)  d_in[1];
    const float* w_e1 = (const float*)d_in[2];
    const float* b_e1 = (const float*)d_in[3];
    const float* w_g1 = (const float*)d_in[4];
    const float* b_g1 = (const float*)d_in[5];
    const float* w_g2 = (const float*)d_in[6];
    const float* b_g2 = (const float*)d_in[7];
    const float* w_e2 = (const float*)d_in[8];
    const float* b_e2 = (const float*)d_in[9];
    const float* w_d1 = (const float*)d_in[10];
    const float* b_d1 = (const float*)d_in[11];
    const float* w_d2 = (const float*)d_in[12];
    const float* b_d2 = (const float*)d_in[13];
    float* out = (float*)d_out;
    const int* src = knn;
    const int* dst = knn + NEDGE;

    __half *p_h0, *p_h1;
    float *p_agg0, *p_agg1, *p_lat, *p_lat2, *p_base, *p_dinv;
    cudaGetSymbolAddress((void**)&p_h0,   g_h0);
    cudaGetSymbolAddress((void**)&p_agg0, g_agg0);
    cudaGetSymbolAddress((void**)&p_h1,   g_h1);
    cudaGetSymbolAddress((void**)&p_agg1, g_agg1);
    cudaGetSymbolAddress((void**)&p_lat,  g_lat);
    cudaGetSymbolAddress((void**)&p_lat2, g_lat2);
    cudaGetSymbolAddress((void**)&p_base, g_base);
    cudaGetSymbolAddress((void**)&p_dinv, g_dinv);

    init_kernel<<<BN / 256, 256>>>();
    cnt_kernel<<<NEDGE / 256, 256>>>(dst);
    scan_kernel<<<1, 1024>>>();
    fill_kernel<<<NEDGE / 256, 256>>>(src, dst);
    cov_e1_kernel<<<BN / 32, 128>>>(x, w_e1, b_e1);

    // GCN layer 1: rows of 64 halves = 8 uint4 slots
    gather_kernel<3><<<(BN * 8) / 256, 256>>>(p_h0, p_agg0);
    gemm_tf32_kernel<C1, C0, false><<<dim3(C1 / 128, BN / 128), 256>>>(
        p_agg0, p_dinv, w_g1, b_g1, p_h1, nullptr);

    // GCN layer 2 + fused max-pool: rows of 128 halves = 16 uint4 slots
    gather_kernel<4><<<(BN * 16) / 256, 256>>>(p_h1, p_agg1);
    gemm_tf32_kernel<C2, C1, true><<<dim3(C2 / 128, BN / 128), 256>>>(
        p_agg1, p_dinv, w_g2, b_g2, nullptr, p_lat);

    e2_kernel<<<NB, C2>>>(p_lat, w_e2, b_e2, p_lat2);
    base_kernel<<<NB * 6, 32>>>(p_lat2, w_d1, w_d2, p_base);
    final_kernel<<<BN / 256, 256>>>(p_base, w_d1, b_d1, w_d2, b_d2, out);
}

// round 13
// speedup vs baseline: 1.2144x; 1.2144x over previous
#include <cuda_runtime.h>
#include <cuda_fp16.h>
#include <math.h>
#include <stdint.h>

#define NB    8
#define NPTS  4096
#define BN    32768
#define NEDGE 524288
#define C0    64
#define C1    128
#define C2    512
#define ROW0  (BN * C0)    // halves per agg0 buffer
#define ROW1  (BN * C1)

// ---------------- scratch ----------------
__device__ __half g_h0[ROW0];          // hs0 = dinv*h0 (fp16)
__device__ __half g_agg0h[4 * ROW0];   // 4 split accumulators, buffer0 seeded with hs0
__device__ __half g_h1[ROW1];
__device__ __half g_agg1h[4 * ROW1];
__device__ float  g_dinv[BN];
__device__ int    g_deg[BN];
__device__ float  g_lat[NB * C2];
__device__ float  g_lat2[NB * C2];
__device__ float  g_base[NB * 6];

__device__ __forceinline__ float selu_f(float v) {
    const float scale = 1.0507009873554805f;
    const float alpha = 1.6732632423543772f;
    return v > 0.0f ? scale * v : scale * alpha * expm1f(v);
}

__device__ __forceinline__ void atomicMaxF(float* addr, float v) {
    if (v >= 0.0f) atomicMax((int*)addr, __float_as_int(v));
    else           atomicMin((unsigned int*)addr, __float_as_uint(v));
}

__device__ __forceinline__ float f2tf32f(float v) {
    uint32_t r;
    asm("cvt.rna.tf32.f32 %0, %1;" : "=r"(r) : "f"(v));
    return __uint_as_float(r);
}

__device__ __forceinline__ uint32_t h2_bits(__half2 h) {
    uint32_t u;
    *reinterpret_cast<__half2*>(&u) = h;
    return u;
}
__device__ __forceinline__ __half2 bits_h2(uint32_t u) {
    return *reinterpret_cast<__half2*>(&u);
}

__device__ __forceinline__ uint4 ldg_nc_u4(const uint4* p) {
    uint4 v;
    asm volatile("ld.global.nc.v4.u32 {%0,%1,%2,%3}, [%4];"
                 : "=r"(v.x), "=r"(v.y), "=r"(v.z), "=r"(v.w) : "l"(p));
    return v;
}

// 16B fp16 vector reduction: 8 halves per instruction
__device__ __forceinline__ void red_add_v4h(__half* p, uint4 v) {
    asm volatile("red.global.add.noftz.v4.f16x2 [%0], {%1,%2,%3,%4};"
                 :: "l"(p), "r"(v.x), "r"(v.y), "r"(v.z), "r"(v.w) : "memory");
}

__device__ __forceinline__ void mma_tf32(float d[4],
                                         uint32_t a0, uint32_t a1, uint32_t a2, uint32_t a3,
                                         uint32_t b0, uint32_t b1) {
    asm volatile("mma.sync.aligned.m16n8k8.row.col.f32.tf32.tf32.f32 "
                 "{%0,%1,%2,%3},{%4,%5,%6,%7},{%8,%9},{%0,%1,%2,%3};"
                 : "+f"(d[0]), "+f"(d[1]), "+f"(d[2]), "+f"(d[3])
                 : "r"(a0), "r"(a1), "r"(a2), "r"(a3), "r"(b0), "r"(b1));
}

// ---------------- init / degree ----------------
__global__ void init_kernel() {
    int i = blockIdx.x * blockDim.x + threadIdx.x;
    if (i < BN) g_deg[i] = 1;
    if (i < NB * C2) g_lat[i] = __int_as_float(0xff800000);
}
__global__ void deg_kernel(const int* __restrict__ dst) {
    int e = blockIdx.x * blockDim.x + threadIdx.x;
    if (e < NEDGE) atomicAdd(&g_deg[dst[e]], 1);
}
__global__ void dinv_kernel() {
    int i = blockIdx.x * blockDim.x + threadIdx.x;
    if (i < BN) g_dinv[i] = rsqrtf((float)g_deg[i]);
}

// ---------------- cov + 12->64 + selu -> hs0 fp16 (writes h0 AND agg0h buffer0) ----------------
__global__ void __launch_bounds__(128)
cov_e1_kernel(const float* __restrict__ x,
              const float* __restrict__ w_e1,
              const float* __restrict__ b_e1) {
    __shared__ float xw[56][3];
    __shared__ float ws[12 * 64];
    __shared__ float bs[64];
    __shared__ float feat_s[32][13];
    __shared__ float out_s[32][68];
    int t = threadIdx.x;
    int blk = blockIdx.x;
    int b = blk >> 7;
    int n_base = (blk & 127) << 5;
    int point0 = blk << 5;

    if (t < 56) {
        int idx = n_base + t - 12;
        idx = min(max(idx, 0), NPTS - 1);
        const float* xp = x + (((size_t)b << 12) + idx) * 3;
        xw[t][0] = xp[0]; xw[t][1] = xp[1]; xw[t][2] = xp[2];
    }
    for (int i = t; i < 12 * 64; i += 128) ws[i] = w_e1[i];
    if (t < 64) bs[t] = b_e1[t];
    __syncthreads();

    if (t < 32) {
        int n = n_base + t;
        float m0 = 0.f, m1 = 0.f, m2 = 0.f, cnt = 0.f;
        #pragma unroll
        for (int w = 0; w < 25; w++) {
            int nn = n + w - 12;
            if (nn >= 0 && nn < NPTS) {
                m0 += xw[t + w][0]; m1 += xw[t + w][1]; m2 += xw[t + w][2];
                cnt += 1.0f;
            }
        }
        float ic = 1.0f / cnt;
        m0 *= ic; m1 *= ic; m2 *= ic;
        float c00=0,c01=0,c02=0,c11=0,c12=0,c22=0;
        #pragma unroll
        for (int w = 0; w < 25; w++) {
            int nn = n + w - 12;
            if (nn >= 0 && nn < NPTS) {
                float d0 = xw[t + w][0] - m0;
                float d1 = xw[t + w][1] - m1;
                float d2 = xw[t + w][2] - m2;
                c00 = fmaf(d0,d0,c00); c01 = fmaf(d0,d1,c01); c02 = fmaf(d0,d2,c02);
                c11 = fmaf(d1,d1,c11); c12 = fmaf(d1,d2,c12); c22 = fmaf(d2,d2,c22);
            }
        }
        const float s = 1.0f / 23.0f;
        feat_s[t][0] = xw[t + 12][0]; feat_s[t][1] = xw[t + 12][1]; feat_s[t][2] = xw[t + 12][2];
        feat_s[t][3] = c00 * s; feat_s[t][4]  = c01 * s; feat_s[t][5]  = c02 * s;
        feat_s[t][6] = c01 * s; feat_s[t][7]  = c11 * s; feat_s[t][8]  = c12 * s;
        feat_s[t][9] = c02 * s; feat_s[t][10] = c12 * s; feat_s[t][11] = c22 * s;
    }
    __syncthreads();

    int pt = t >> 2, quarter = t & 3;
    float dv = g_dinv[point0 + pt];
    float feat[12];
    #pragma unroll
    for (int k = 0; k < 12; k++) feat[k] = feat_s[pt][k];
    #pragma unroll
    for (int jj = 0; jj < 16; jj++) {
        int j = (quarter << 4) + jj;
        float acc = bs[j];
        #pragma unroll
        for (int k = 0; k < 12; k++) acc = fmaf(feat[k], ws[k * 64 + j], acc);
        out_s[pt][j] = dv * selu_f(acc);
    }
    __syncthreads();

    for (int i = t; i < 256; i += 128) {
        int row = i >> 3, seg = i & 7;
        const float* src = &out_s[row][seg << 3];
        uint4 pk;
        pk.x = h2_bits(__floats2half2_rn(src[0], src[1]));
        pk.y = h2_bits(__floats2half2_rn(src[2], src[3]));
        pk.z = h2_bits(__floats2half2_rn(src[4], src[5]));
        pk.w = h2_bits(__floats2half2_rn(src[6], src[7]));
        size_t goff = (size_t)(point0 + row) * 64 + (seg << 3);
        *reinterpret_cast<uint4*>(g_h0 + goff)     = pk;
        *reinterpret_cast<uint4*>(g_agg0h + goff)  = pk;   // buffer 0 seed
    }
}

// ---------------- edge scatter fp16, 4-way split: agg[e&3][d] += hs[s] ----------------
// Chunk = 8 halves (16B). LOGC = log2(chunks per row); row halves = 8<<LOGC.
template<int LOGC>
__global__ void edge_kernel(const int* __restrict__ src, const int* __restrict__ dst,
                            const __half* __restrict__ hs, __half* __restrict__ agg,
                            int bufstride) {
    int idx = blockIdx.x * blockDim.x + threadIdx.x;
    int e = idx >> LOGC;
    int g = idx & ((1 << LOGC) - 1);
    if (e >= NEDGE) return;
    int s = src[e], d = dst[e];
    int buf = e & 3;
    uint4 v = ldg_nc_u4(reinterpret_cast<const uint4*>(hs + ((size_t)s << (LOGC + 3))) + g);
    red_add_v4h(agg + (size_t)buf * bufstride + ((size_t)d << (LOGC + 3)) + (g << 3), v);
}

// ---------------- single-pass TF32 GEMM, 4-buffer fp16 A, 128x128 tile, double-buffered ----------------
// A_eff[row] = dinv[row] * sum_{b=0..3} Ab[row];  out = selu(A_eff @ W + bias)
// !DO_MAX: writes fp16 to O1 (h) and Oseed (agg buffer0).  DO_MAX: fused max-pool -> lat.
template<int N, int K, bool DO_MAX>
__global__ void __launch_bounds__(256, 2)
gemm_tf32_kernel(const __half* __restrict__ A, int bufstride,
                 const float* __restrict__ dinv,
                 const float* __restrict__ Wt, const float* __restrict__ bias,
                 __half* __restrict__ O1, __half* __restrict__ Oseed,
                 float* __restrict__ lat) {
    __shared__ float Ah[2][128][20];
    __shared__ float Bh[2][16][132];

    int tid = threadIdx.x;
    int warp = tid >> 5, lane = tid & 31;
    int wm = warp >> 2, wn = warp & 3;
    int g = lane >> 2, c = lane & 3;
    int row0 = blockIdx.y * 128, col0 = blockIdx.x * 128;

    int ar = tid >> 1;
    int ak = (tid & 1) << 3;
    float dv = dinv[row0 + ar];
    int bkr = tid >> 4;
    int bc0 = (tid & 15) << 3;

    const int KT = K / 16;
    const uint4* A4 = reinterpret_cast<const uint4*>(A);
    int bs4 = bufstride >> 3;   // buffer stride in uint4

    float d[4][4][4];
    #pragma unroll
    for (int mt = 0; mt < 4; mt++)
        #pragma unroll
        for (int nt = 0; nt < 4; nt++)
            #pragma unroll
            for (int r = 0; r < 4; r++) d[mt][nt][r] = 0.0f;

    auto load_a = [&](int koff, uint4 raw[4]) {
        size_t off = ((size_t)(row0 + ar) * K + koff + ak) >> 3;
        #pragma unroll
        for (int b = 0; b < 4; b++) raw[b] = ldg_nc_u4(A4 + (size_t)b * bs4 + off);
    };
    auto stage_a = [&](int buf, uint4 raw[4]) {
        float acc[8] = {0,0,0,0,0,0,0,0};
        #pragma unroll
        for (int b = 0; b < 4; b++) {
            uint32_t w[4] = {raw[b].x, raw[b].y, raw[b].z, raw[b].w};
            #pragma unroll
            for (int j = 0; j < 4; j++) {
                float2 f = __half22float2(bits_h2(w[j]));
                acc[2 * j] += f.x; acc[2 * j + 1] += f.y;
            }
        }
        #pragma unroll
        for (int i = 0; i < 8; i++) Ah[buf][ar][ak + i] = f2tf32f(dv * acc[i]);
    };
    auto stage_b = [&](int buf, float4 b0, float4 b1) {
        Bh[buf][bkr][bc0 + 0] = f2tf32f(b0.x); Bh[buf][bkr][bc0 + 1] = f2tf32f(b0.y);
        Bh[buf][bkr][bc0 + 2] = f2tf32f(b0.z); Bh[buf][bkr][bc0 + 3] = f2tf32f(b0.w);
        Bh[buf][bkr][bc0 + 4] = f2tf32f(b1.x); Bh[buf][bkr][bc0 + 5] = f2tf32f(b1.y);
        Bh[buf][bkr][bc0 + 6] = f2tf32f(b1.z); Bh[buf][bkr][bc0 + 7] = f2tf32f(b1.w);
    };

    {
        uint4 raw[4];
        load_a(0, raw);
        stage_a(0, raw);
        float4 b0 = *reinterpret_cast<const float4*>(Wt + (size_t)bkr * N + col0 + bc0);
        float4 b1 = *reinterpret_cast<const float4*>(Wt + (size_t)bkr * N + col0 + bc0 + 4);
        stage_b(0, b0, b1);
    }
    __syncthreads();

    for (int kt = 0; kt < KT; kt++) {
        int cur = kt & 1, nxt = cur ^ 1;
        uint4 raw[4]; float4 b0, b1;
        bool more = (kt + 1 < KT);
        if (more) {
            int koff = (kt + 1) * 16;
            load_a(koff, raw);
            b0 = *reinterpret_cast<const float4*>(Wt + (size_t)(koff + bkr) * N + col0 + bc0);
            b1 = *reinterpret_cast<const float4*>(Wt + (size_t)(koff + bkr) * N + col0 + bc0 + 4);
        }

        #pragma unroll
        for (int ks = 0; ks < 2; ks++) {
            int k0 = ks << 3;
            uint32_t af[4][4];
            #pragma unroll
            for (int mt = 0; mt < 4; mt++) {
                int rm = wm * 64 + mt * 16;
                af[mt][0] = __float_as_uint(Ah[cur][rm + g][k0 + c]);
                af[mt][1] = __float_as_uint(Ah[cur][rm + g + 8][k0 + c]);
                af[mt][2] = __float_as_uint(Ah[cur][rm + g][k0 + c + 4]);
                af[mt][3] = __float_as_uint(Ah[cur][rm + g + 8][k0 + c + 4]);
            }
            uint32_t bf[4][2];
            #pragma unroll
            for (int nt = 0; nt < 4; nt++) {
                int nb = wn * 32 + nt * 8;
                bf[nt][0] = __float_as_uint(Bh[cur][k0 + c][nb + g]);
                bf[nt][1] = __float_as_uint(Bh[cur][k0 + c + 4][nb + g]);
            }
            #pragma unroll
            for (int mt = 0; mt < 4; mt++)
                #pragma unroll
                for (int nt = 0; nt < 4; nt++)
                    mma_tf32(d[mt][nt], af[mt][0], af[mt][1], af[mt][2], af[mt][3],
                             bf[nt][0], bf[nt][1]);
        }

        if (more) { stage_a(nxt, raw); stage_b(nxt, b0, b1); }
        __syncthreads();
    }

    float bv[4][2];
    #pragma unroll
    for (int nt = 0; nt < 4; nt++) {
        int cc = col0 + wn * 32 + nt * 8 + (c << 1);
        bv[nt][0] = bias[cc];
        bv[nt][1] = bias[cc + 1];
    }

    if (!DO_MAX) {
        #pragma unroll
        for (int mt = 0; mt < 4; mt++) {
            int rbase = row0 + wm * 64 + mt * 16;
            #pragma unroll
            for (int half = 0; half < 2; half++) {
                int r = rbase + g + half * 8;
                float dv2 = dinv[r];
                #pragma unroll
                for (int nt = 0; nt < 4; nt++) {
                    int cc = col0 + wn * 32 + nt * 8 + (c << 1);
                    __half2 o = __floats2half2_rn(
                        dv2 * selu_f(d[mt][nt][half * 2 + 0] + bv[nt][0]),
                        dv2 * selu_f(d[mt][nt][half * 2 + 1] + bv[nt][1]));
                    size_t addr = (size_t)r * N + cc;
                    *reinterpret_cast<__half2*>(O1 + addr)    = o;
                    *reinterpret_cast<__half2*>(Oseed + addr) = o;   // agg buffer0 seed
                }
            }
        }
    } else {
        float mv[4][2];
        #pragma unroll
        for (int nt = 0; nt < 4; nt++) { mv[nt][0] = mv[nt][1] = __int_as_float(0xff800000); }
        #pragma unroll
        for (int mt = 0; mt < 4; mt++)
            #pragma unroll
            for (int nt = 0; nt < 4; nt++) {
                mv[nt][0] = fmaxf(mv[nt][0], fmaxf(selu_f(d[mt][nt][0] + bv[nt][0]),
                                                   selu_f(d[mt][nt][2] + bv[nt][0])));
                mv[nt][1] = fmaxf(mv[nt][1], fmaxf(selu_f(d[mt][nt][1] + bv[nt][1]),
                                                   selu_f(d[mt][nt][3] + bv[nt][1])));
            }
        #pragma unroll
        for (int off = 4; off <= 16; off <<= 1)
            #pragma unroll
            for (int nt = 0; nt < 4; nt++) {
                mv[nt][0] = fmaxf(mv[nt][0], __shfl_xor_sync(0xffffffffu, mv[nt][0], off));
                mv[nt][1] = fmaxf(mv[nt][1], __shfl_xor_sync(0xffffffffu, mv[nt][1], off));
            }
        if (lane < 4) {
            int b = row0 >> 12;
            #pragma unroll
            for (int nt = 0; nt < 4; nt++) {
                int cc = col0 + wn * 32 + nt * 8 + (lane << 1);
                atomicMaxF(&lat[b * C2 + cc], mv[nt][0]);
                atomicMaxF(&lat[b * C2 + cc + 1], mv[nt][1]);
            }
        }
    }
}

// ---------------- lat2 = selu(lat @ w_e2 + b_e2) ----------------
__global__ void e2_kernel(const float* __restrict__ lat, const float* __restrict__ w,
                          const float* __restrict__ bias, float* __restrict__ lat2) {
    __shared__ float row[C2];
    int c = threadIdx.x;
    row[c] = lat[blockIdx.x * C2 + c];
    __syncthreads();
    float acc = bias[c];
    #pragma unroll 8
    for (int k = 0; k < C2; k++) acc = fmaf(row[k], w[k * C2 + c], acc);
    lat2[blockIdx.x * C2 + c] = selu_f(acc);
}

// ---------------- decoder ----------------
__global__ void base_kernel(const float* __restrict__ lat2,
                            const float* __restrict__ w_d1,
                            const float* __restrict__ w_d2,
                            float* __restrict__ base) {
    int o = blockIdx.x;
    int b = o / 6, t = o % 6, j = t % 3;
    const float* w = (t < 3) ? w_d1 : w_d2;
    int lane = threadIdx.x;
    float s = 0.0f;
    for (int c = lane; c < C2; c += 32) s += lat2[b * C2 + c] * w[c * 3 + j];
    #pragma unroll
    for (int off = 16; off > 0; off >>= 1) s += __shfl_xor_sync(0xffffffffu, s, off);
    if (lane == 0) base[b * 6 + t] = s;
}

__global__ void final_kernel(const float* __restrict__ base,
                             const float* __restrict__ w_d1, const float* __restrict__ b_d1,
                             const float* __restrict__ w_d2, const float* __restrict__ b_d2,
                             float* __restrict__ out) {
    int idx = blockIdx.x * blockDim.x + threadIdx.x;
    int b = idx >> 12, n = idx & 4095;
    int ix = n / 46, iy = n % 46;
    float y0 = 1.0f + ix * (119.0f / 90.0f);
    float y1 = 1.0f + iy * (59.0f / 45.0f);
    float kk[3];
    #pragma unroll
    for (int j = 0; j < 3; j++)
        kk[j] = selu_f(base[b * 6 + j] + y0 * w_d1[512 * 3 + j] + y1 * w_d1[513 * 3 + j] + b_d1[j]);
    #pragma unroll
    for (int j = 0; j < 3; j++) {
        float v = base[b * 6 + 3 + j]
                + kk[0] * w_d2[512 * 3 + j]
                + kk[1] * w_d2[513 * 3 + j]
                + kk[2] * w_d2[514 * 3 + j]
                + b_d2[j];
        out[(size_t)idx * 3 + j] = selu_f(v);
    }
}

// ---------------- launch ----------------
extern "C" void kernel_launch(void* const* d_in, const int* in_sizes, int n_in,
                              void* d_out, int out_size) {
    const float* x    = (const float*)d_in[0];
    const int*   knn  = (const int*)  d_in[1];
    const float* w_e1 = (const float*)d_in[2];
    const float* b_e1 = (const float*)d_in[3];
    const float* w_g1 = (const float*)d_in[4];
    const float* b_g1 = (const float*)d_in[5];
    const float* w_g2 = (const float*)d_in[6];
    const float* b_g2 = (const float*)d_in[7];
    const float* w_e2 = (const float*)d_in[8];
    const float* b_e2 = (const float*)d_in[9];
    const float* w_d1 = (const float*)d_in[10];
    const float* b_d1 = (const float*)d_in[11];
    const float* w_d2 = (const float*)d_in[12];
    const float* b_d2 = (const float*)d_in[13];
    float* out = (float*)d_out;
    const int* src = knn;
    const int* dst = knn + NEDGE;

    __half *p_h0, *p_agg0h, *p_h1, *p_agg1h;
    float *p_lat, *p_lat2, *p_base, *p_dinv;
    cudaGetSymbolAddress((void**)&p_h0,    g_h0);
    cudaGetSymbolAddress((void**)&p_agg0h, g_agg0h);
    cudaGetSymbolAddress((void**)&p_h1,    g_h1);
    cudaGetSymbolAddress((void**)&p_agg1h, g_agg1h);
    cudaGetSymbolAddress((void**)&p_lat,   g_lat);
    cudaGetSymbolAddress((void**)&p_lat2,  g_lat2);
    cudaGetSymbolAddress((void**)&p_base,  g_base);
    cudaGetSymbolAddress((void**)&p_dinv,  g_dinv);

    // zero split buffers 1..3 (buffer 0 is seeded by producers)
    cudaMemsetAsync(p_agg0h + ROW0, 0, (size_t)3 * ROW0 * sizeof(__half));
    cudaMemsetAsync(p_agg1h + ROW1, 0, (size_t)3 * ROW1 * sizeof(__half));

    init_kernel<<<BN / 256, 256>>>();
    deg_kernel<<<NEDGE / 256, 256>>>(dst);
    dinv_kernel<<<BN / 256, 256>>>();
    cov_e1_kernel<<<BN / 32, 128>>>(x, w_e1, b_e1);

    // GCN layer 1: 64 halves/row = 8 chunks of 8 halves
    edge_kernel<3><<<(NEDGE * 8) / 256, 256>>>(src, dst, p_h0, p_agg0h, ROW0);
    gemm_tf32_kernel<C1, C0, false><<<dim3(C1 / 128, BN / 128), 256>>>(
        p_agg0h, ROW0, p_dinv, w_g1, b_g1, p_h1, p_agg1h, nullptr);

    // GCN layer 2 + fused max-pool: 128 halves/row = 16 chunks of 8 halves
    edge_kernel<4><<<(NEDGE * 16) / 256, 256>>>(src, dst, p_h1, p_agg1h, ROW1);
    gemm_tf32_kernel<C2, C1, true><<<dim3(C2 / 128, BN / 128), 256>>>(
        p_agg1h, ROW1, p_dinv, w_g2, b_g2, nullptr, nullptr, p_lat);

    e2_kernel<<<NB, C2>>>(p_lat, w_e2, b_e2, p_lat2);
    base_kernel<<<NB * 6, 32>>>(p_lat2, w_d1, w_d2, p_base);
    final_kernel<<<BN / 256, 256>>>(p_base, w_d1, b_d1, w_d2, b_d2, out);
}

// round 14
// speedup vs baseline: 1.3601x; 1.1200x over previous
#include <cuda_runtime.h>
#include <cuda_fp16.h>
#include <math.h>
#include <stdint.h>

#define NB    8
#define NPTS  4096
#define BN    32768
#define NEDGE 524288
#define C0    64
#define C1    128
#define C2    512
#define ROW0  (BN * C0)    // halves per agg0 buffer
#define ROW1  (BN * C1)

// ---------------- scratch ----------------
__device__ __half g_h0[ROW0];          // hs0 = dinv*h0 (fp16)
__device__ __half g_agg0h[2 * ROW0];   // 2 split accumulators, buffer0 seeded with hs0
__device__ __half g_h1[ROW1];
__device__ __half g_agg1h[2 * ROW1];
__device__ float  g_dinv[BN];
__device__ int    g_deg[BN];
__device__ float  g_lat[NB * C2];
__device__ float  g_lat2[NB * C2];
__device__ float  g_base[NB * 6];

__device__ __forceinline__ float selu_f(float v) {
    const float scale = 1.0507009873554805f;
    const float alpha = 1.6732632423543772f;
    return v > 0.0f ? scale * v : scale * alpha * expm1f(v);
}

__device__ __forceinline__ void atomicMaxF(float* addr, float v) {
    if (v >= 0.0f) atomicMax((int*)addr, __float_as_int(v));
    else           atomicMin((unsigned int*)addr, __float_as_uint(v));
}

__device__ __forceinline__ float f2tf32f(float v) {
    uint32_t r;
    asm("cvt.rna.tf32.f32 %0, %1;" : "=r"(r) : "f"(v));
    return __uint_as_float(r);
}

__device__ __forceinline__ uint32_t h2_bits(__half2 h) {
    uint32_t u;
    *reinterpret_cast<__half2*>(&u) = h;
    return u;
}
__device__ __forceinline__ __half2 bits_h2(uint32_t u) {
    return *reinterpret_cast<__half2*>(&u);
}

__device__ __forceinline__ uint4 ldg_nc_u4(const uint4* p) {
    uint4 v;
    asm volatile("ld.global.nc.v4.u32 {%0,%1,%2,%3}, [%4];"
                 : "=r"(v.x), "=r"(v.y), "=r"(v.z), "=r"(v.w) : "l"(p));
    return v;
}

// 16B fp16 vector reduction: 8 halves per instruction
__device__ __forceinline__ void red_add_v4h(__half* p, uint4 v) {
    asm volatile("red.global.add.noftz.v4.f16x2 [%0], {%1,%2,%3,%4};"
                 :: "l"(p), "r"(v.x), "r"(v.y), "r"(v.z), "r"(v.w) : "memory");
}

__device__ __forceinline__ void mma_tf32(float d[4],
                                         uint32_t a0, uint32_t a1, uint32_t a2, uint32_t a3,
                                         uint32_t b0, uint32_t b1) {
    asm volatile("mma.sync.aligned.m16n8k8.row.col.f32.tf32.tf32.f32 "
                 "{%0,%1,%2,%3},{%4,%5,%6,%7},{%8,%9},{%0,%1,%2,%3};"
                 : "+f"(d[0]), "+f"(d[1]), "+f"(d[2]), "+f"(d[3])
                 : "r"(a0), "r"(a1), "r"(a2), "r"(a3), "r"(b0), "r"(b1));
}

// ---------------- init / degree ----------------
__global__ void init_kernel() {
    int i = blockIdx.x * blockDim.x + threadIdx.x;
    if (i < BN) g_deg[i] = 1;
    if (i < NB * C2) g_lat[i] = __int_as_float(0xff800000);
}
__global__ void deg_kernel(const int* __restrict__ dst) {
    int e = blockIdx.x * blockDim.x + threadIdx.x;
    if (e < NEDGE) atomicAdd(&g_deg[dst[e]], 1);
}
__global__ void dinv_kernel() {
    int i = blockIdx.x * blockDim.x + threadIdx.x;
    if (i < BN) g_dinv[i] = rsqrtf((float)g_deg[i]);
}

// ---------------- cov + 12->64 + selu -> hs0 fp16 (writes h0 AND agg0h buffer0) ----------------
__global__ void __launch_bounds__(128)
cov_e1_kernel(const float* __restrict__ x,
              const float* __restrict__ w_e1,
              const float* __restrict__ b_e1) {
    __shared__ float xw[56][3];
    __shared__ float ws[12 * 64];
    __shared__ float bs[64];
    __shared__ float feat_s[32][13];
    __shared__ float out_s[32][68];
    int t = threadIdx.x;
    int blk = blockIdx.x;
    int b = blk >> 7;
    int n_base = (blk & 127) << 5;
    int point0 = blk << 5;

    if (t < 56) {
        int idx = n_base + t - 12;
        idx = min(max(idx, 0), NPTS - 1);
        const float* xp = x + (((size_t)b << 12) + idx) * 3;
        xw[t][0] = xp[0]; xw[t][1] = xp[1]; xw[t][2] = xp[2];
    }
    for (int i = t; i < 12 * 64; i += 128) ws[i] = w_e1[i];
    if (t < 64) bs[t] = b_e1[t];
    __syncthreads();

    if (t < 32) {
        int n = n_base + t;
        float m0 = 0.f, m1 = 0.f, m2 = 0.f, cnt = 0.f;
        #pragma unroll
        for (int w = 0; w < 25; w++) {
            int nn = n + w - 12;
            if (nn >= 0 && nn < NPTS) {
                m0 += xw[t + w][0]; m1 += xw[t + w][1]; m2 += xw[t + w][2];
                cnt += 1.0f;
            }
        }
        float ic = 1.0f / cnt;
        m0 *= ic; m1 *= ic; m2 *= ic;
        float c00=0,c01=0,c02=0,c11=0,c12=0,c22=0;
        #pragma unroll
        for (int w = 0; w < 25; w++) {
            int nn = n + w - 12;
            if (nn >= 0 && nn < NPTS) {
                float d0 = xw[t + w][0] - m0;
                float d1 = xw[t + w][1] - m1;
                float d2 = xw[t + w][2] - m2;
                c00 = fmaf(d0,d0,c00); c01 = fmaf(d0,d1,c01); c02 = fmaf(d0,d2,c02);
                c11 = fmaf(d1,d1,c11); c12 = fmaf(d1,d2,c12); c22 = fmaf(d2,d2,c22);
            }
        }
        const float s = 1.0f / 23.0f;
        feat_s[t][0] = xw[t + 12][0]; feat_s[t][1] = xw[t + 12][1]; feat_s[t][2] = xw[t + 12][2];
        feat_s[t][3] = c00 * s; feat_s[t][4]  = c01 * s; feat_s[t][5]  = c02 * s;
        feat_s[t][6] = c01 * s; feat_s[t][7]  = c11 * s; feat_s[t][8]  = c12 * s;
        feat_s[t][9] = c02 * s; feat_s[t][10] = c12 * s; feat_s[t][11] = c22 * s;
    }
    __syncthreads();

    int pt = t >> 2, quarter = t & 3;
    float dv = g_dinv[point0 + pt];
    float feat[12];
    #pragma unroll
    for (int k = 0; k < 12; k++) feat[k] = feat_s[pt][k];
    #pragma unroll
    for (int jj = 0; jj < 16; jj++) {
        int j = (quarter << 4) + jj;
        float acc = bs[j];
        #pragma unroll
        for (int k = 0; k < 12; k++) acc = fmaf(feat[k], ws[k * 64 + j], acc);
        out_s[pt][j] = dv * selu_f(acc);
    }
    __syncthreads();

    for (int i = t; i < 256; i += 128) {
        int row = i >> 3, seg = i & 7;
        const float* src = &out_s[row][seg << 3];
        uint4 pk;
        pk.x = h2_bits(__floats2half2_rn(src[0], src[1]));
        pk.y = h2_bits(__floats2half2_rn(src[2], src[3]));
        pk.z = h2_bits(__floats2half2_rn(src[4], src[5]));
        pk.w = h2_bits(__floats2half2_rn(src[6], src[7]));
        size_t goff = (size_t)(point0 + row) * 64 + (seg << 3);
        *reinterpret_cast<uint4*>(g_h0 + goff)     = pk;
        *reinterpret_cast<uint4*>(g_agg0h + goff)  = pk;   // buffer 0 seed
    }
}

// ---------------- edge scatter fp16, 2-way split: agg[e&1][d] += hs[s] ----------------
// Chunk = 8 halves (16B). LOGC = log2(chunks per row); row halves = 8<<LOGC.
template<int LOGC>
__global__ void edge_kernel(const int* __restrict__ src, const int* __restrict__ dst,
                            const __half* __restrict__ hs, __half* __restrict__ agg,
                            int bufstride) {
    int idx = blockIdx.x * blockDim.x + threadIdx.x;
    int e = idx >> LOGC;
    int g = idx & ((1 << LOGC) - 1);
    if (e >= NEDGE) return;
    int s = src[e], d = dst[e];
    int buf = e & 1;
    uint4 v = ldg_nc_u4(reinterpret_cast<const uint4*>(hs + ((size_t)s << (LOGC + 3))) + g);
    red_add_v4h(agg + (size_t)buf * bufstride + ((size_t)d << (LOGC + 3)) + (g << 3), v);
}

// ---------------- single-pass TF32 GEMM, 2-buffer fp16 A, 128x128 tile, double-buffered ----------------
// A_eff[row] = dinv[row] * (A0[row] + A1[row]) (f32 merge);  out = selu(A_eff @ W + bias)
// !DO_MAX: writes fp16 to O1 (h) and Oseed (next agg buffer0).  DO_MAX: fused max-pool -> lat.
template<int N, int K, bool DO_MAX>
__global__ void __launch_bounds__(256, 2)
gemm_tf32_kernel(const __half* __restrict__ A, int bufstride,
                 const float* __restrict__ dinv,
                 const float* __restrict__ Wt, const float* __restrict__ bias,
                 __half* __restrict__ O1, __half* __restrict__ Oseed,
                 float* __restrict__ lat) {
    __shared__ float Ah[2][128][20];
    __shared__ float Bh[2][16][132];

    int tid = threadIdx.x;
    int warp = tid >> 5, lane = tid & 31;
    int wm = warp >> 2, wn = warp & 3;
    int g = lane >> 2, c = lane & 3;
    int row0 = blockIdx.y * 128, col0 = blockIdx.x * 128;

    int ar = tid >> 1;
    int ak = (tid & 1) << 3;
    float dv = dinv[row0 + ar];
    int bkr = tid >> 4;
    int bc0 = (tid & 15) << 3;

    const int KT = K / 16;
    const uint4* A4 = reinterpret_cast<const uint4*>(A);
    int bs4 = bufstride >> 3;   // buffer stride in uint4

    float d[4][4][4];
    #pragma unroll
    for (int mt = 0; mt < 4; mt++)
        #pragma unroll
        for (int nt = 0; nt < 4; nt++)
            #pragma unroll
            for (int r = 0; r < 4; r++) d[mt][nt][r] = 0.0f;

    auto load_a = [&](int koff, uint4 raw[2]) {
        size_t off = ((size_t)(row0 + ar) * K + koff + ak) >> 3;
        raw[0] = ldg_nc_u4(A4 + off);
        raw[1] = ldg_nc_u4(A4 + (size_t)bs4 + off);
    };
    auto stage_a = [&](int buf, uint4 raw[2]) {
        uint32_t w0[4] = {raw[0].x, raw[0].y, raw[0].z, raw[0].w};
        uint32_t w1[4] = {raw[1].x, raw[1].y, raw[1].z, raw[1].w};
        #pragma unroll
        for (int j = 0; j < 4; j++) {
            float2 f0 = __half22float2(bits_h2(w0[j]));
            float2 f1 = __half22float2(bits_h2(w1[j]));
            Ah[buf][ar][ak + 2 * j]     = f2tf32f(dv * (f0.x + f1.x));
            Ah[buf][ar][ak + 2 * j + 1] = f2tf32f(dv * (f0.y + f1.y));
        }
    };
    auto stage_b = [&](int buf, float4 b0, float4 b1) {
        Bh[buf][bkr][bc0 + 0] = f2tf32f(b0.x); Bh[buf][bkr][bc0 + 1] = f2tf32f(b0.y);
        Bh[buf][bkr][bc0 + 2] = f2tf32f(b0.z); Bh[buf][bkr][bc0 + 3] = f2tf32f(b0.w);
        Bh[buf][bkr][bc0 + 4] = f2tf32f(b1.x); Bh[buf][bkr][bc0 + 5] = f2tf32f(b1.y);
        Bh[buf][bkr][bc0 + 6] = f2tf32f(b1.z); Bh[buf][bkr][bc0 + 7] = f2tf32f(b1.w);
    };

    {
        uint4 raw[2];
        load_a(0, raw);
        stage_a(0, raw);
        float4 b0 = *reinterpret_cast<const float4*>(Wt + (size_t)bkr * N + col0 + bc0);
        float4 b1 = *reinterpret_cast<const float4*>(Wt + (size_t)bkr * N + col0 + bc0 + 4);
        stage_b(0, b0, b1);
    }
    __syncthreads();

    for (int kt = 0; kt < KT; kt++) {
        int cur = kt & 1, nxt = cur ^ 1;
        uint4 raw[2]; float4 b0, b1;
        bool more = (kt + 1 < KT);
        if (more) {
            int koff = (kt + 1) * 16;
            load_a(koff, raw);
            b0 = *reinterpret_cast<const float4*>(Wt + (size_t)(koff + bkr) * N + col0 + bc0);
            b1 = *reinterpret_cast<const float4*>(Wt + (size_t)(koff + bkr) * N + col0 + bc0 + 4);
        }

        #pragma unroll
        for (int ks = 0; ks < 2; ks++) {
            int k0 = ks << 3;
            uint32_t af[4][4];
            #pragma unroll
            for (int mt = 0; mt < 4; mt++) {
                int rm = wm * 64 + mt * 16;
                af[mt][0] = __float_as_uint(Ah[cur][rm + g][k0 + c]);
                af[mt][1] = __float_as_uint(Ah[cur][rm + g + 8][k0 + c]);
                af[mt][2] = __float_as_uint(Ah[cur][rm + g][k0 + c + 4]);
                af[mt][3] = __float_as_uint(Ah[cur][rm + g + 8][k0 + c + 4]);
            }
            uint32_t bf[4][2];
            #pragma unroll
            for (int nt = 0; nt < 4; nt++) {
                int nb = wn * 32 + nt * 8;
                bf[nt][0] = __float_as_uint(Bh[cur][k0 + c][nb + g]);
                bf[nt][1] = __float_as_uint(Bh[cur][k0 + c + 4][nb + g]);
            }
            #pragma unroll
            for (int mt = 0; mt < 4; mt++)
                #pragma unroll
                for (int nt = 0; nt < 4; nt++)
                    mma_tf32(d[mt][nt], af[mt][0], af[mt][1], af[mt][2], af[mt][3],
                             bf[nt][0], bf[nt][1]);
        }

        if (more) { stage_a(nxt, raw); stage_b(nxt, b0, b1); }
        __syncthreads();
    }

    float bv[4][2];
    #pragma unroll
    for (int nt = 0; nt < 4; nt++) {
        int cc = col0 + wn * 32 + nt * 8 + (c << 1);
        bv[nt][0] = bias[cc];
        bv[nt][1] = bias[cc + 1];
    }

    if (!DO_MAX) {
        #pragma unroll
        for (int mt = 0; mt < 4; mt++) {
            int rbase = row0 + wm * 64 + mt * 16;
            #pragma unroll
            for (int half = 0; half < 2; half++) {
                int r = rbase + g + half * 8;
                float dv2 = dinv[r];
                #pragma unroll
                for (int nt = 0; nt < 4; nt++) {
                    int cc = col0 + wn * 32 + nt * 8 + (c << 1);
                    __half2 o = __floats2half2_rn(
                        dv2 * selu_f(d[mt][nt][half * 2 + 0] + bv[nt][0]),
                        dv2 * selu_f(d[mt][nt][half * 2 + 1] + bv[nt][1]));
                    size_t addr = (size_t)r * N + cc;
                    *reinterpret_cast<__half2*>(O1 + addr)    = o;
                    *reinterpret_cast<__half2*>(Oseed + addr) = o;   // next agg buffer0 seed
                }
            }
        }
    } else {
        float mv[4][2];
        #pragma unroll
        for (int nt = 0; nt < 4; nt++) { mv[nt][0] = mv[nt][1] = __int_as_float(0xff800000); }
        #pragma unroll
        for (int mt = 0; mt < 4; mt++)
            #pragma unroll
            for (int nt = 0; nt < 4; nt++) {
                mv[nt][0] = fmaxf(mv[nt][0], fmaxf(selu_f(d[mt][nt][0] + bv[nt][0]),
                                                   selu_f(d[mt][nt][2] + bv[nt][0])));
                mv[nt][1] = fmaxf(mv[nt][1], fmaxf(selu_f(d[mt][nt][1] + bv[nt][1]),
                                                   selu_f(d[mt][nt][3] + bv[nt][1])));
            }
        #pragma unroll
        for (int off = 4; off <= 16; off <<= 1)
            #pragma unroll
            for (int nt = 0; nt < 4; nt++) {
                mv[nt][0] = fmaxf(mv[nt][0], __shfl_xor_sync(0xffffffffu, mv[nt][0], off));
                mv[nt][1] = fmaxf(mv[nt][1], __shfl_xor_sync(0xffffffffu, mv[nt][1], off));
            }
        if (lane < 4) {
            int b = row0 >> 12;
            #pragma unroll
            for (int nt = 0; nt < 4; nt++) {
                int cc = col0 + wn * 32 + nt * 8 + (lane << 1);
                atomicMaxF(&lat[b * C2 + cc], mv[nt][0]);
                atomicMaxF(&lat[b * C2 + cc + 1], mv[nt][1]);
            }
        }
    }
}

// ---------------- lat2 = selu(lat @ w_e2 + b_e2) ----------------
__global__ void e2_kernel(const float* __restrict__ lat, const float* __restrict__ w,
                          const float* __restrict__ bias, float* __restrict__ lat2) {
    __shared__ float row[C2];
    int c = threadIdx.x;
    row[c] = lat[blockIdx.x * C2 + c];
    __syncthreads();
    float acc = bias[c];
    #pragma unroll 8
    for (int k = 0; k < C2; k++) acc = fmaf(row[k], w[k * C2 + c], acc);
    lat2[blockIdx.x * C2 + c] = selu_f(acc);
}

// ---------------- decoder ----------------
__global__ void base_kernel(const float* __restrict__ lat2,
                            const float* __restrict__ w_d1,
                            const float* __restrict__ w_d2,
                            float* __restrict__ base) {
    int o = blockIdx.x;
    int b = o / 6, t = o % 6, j = t % 3;
    const float* w = (t < 3) ? w_d1 : w_d2;
    int lane = threadIdx.x;
    float s = 0.0f;
    for (int c = lane; c < C2; c += 32) s += lat2[b * C2 + c] * w[c * 3 + j];
    #pragma unroll
    for (int off = 16; off > 0; off >>= 1) s += __shfl_xor_sync(0xffffffffu, s, off);
    if (lane == 0) base[b * 6 + t] = s;
}

__global__ void final_kernel(const float* __restrict__ base,
                             const float* __restrict__ w_d1, const float* __restrict__ b_d1,
                             const float* __restrict__ w_d2, const float* __restrict__ b_d2,
                             float* __restrict__ out) {
    int idx = blockIdx.x * blockDim.x + threadIdx.x;
    int b = idx >> 12, n = idx & 4095;
    int ix = n / 46, iy = n % 46;
    float y0 = 1.0f + ix * (119.0f / 90.0f);
    float y1 = 1.0f + iy * (59.0f / 45.0f);
    float kk[3];
    #pragma unroll
    for (int j = 0; j < 3; j++)
        kk[j] = selu_f(base[b * 6 + j] + y0 * w_d1[512 * 3 + j] + y1 * w_d1[513 * 3 + j] + b_d1[j]);
    #pragma unroll
    for (int j = 0; j < 3; j++) {
        float v = base[b * 6 + 3 + j]
                + kk[0] * w_d2[512 * 3 + j]
                + kk[1] * w_d2[513 * 3 + j]
                + kk[2] * w_d2[514 * 3 + j]
                + b_d2[j];
        out[(size_t)idx * 3 + j] = selu_f(v);
    }
}

// ---------------- launch ----------------
extern "C" void kernel_launch(void* const* d_in, const int* in_sizes, int n_in,
                              void* d_out, int out_size) {
    const float* x    = (const float*)d_in[0];
    const int*   knn  = (const int*)  d_in[1];
    const float* w_e1 = (const float*)d_in[2];
    const float* b_e1 = (const float*)d_in[3];
    const float* w_g1 = (const float*)d_in[4];
    const float* b_g1 = (const float*)d_in[5];
    const float* w_g2 = (const float*)d_in[6];
    const float* b_g2 = (const float*)d_in[7];
    const float* w_e2 = (const float*)d_in[8];
    const float* b_e2 = (const float*)d_in[9];
    const float* w_d1 = (const float*)d_in[10];
    const float* b_d1 = (const float*)d_in[11];
    const float* w_d2 = (const float*)d_in[12];
    const float* b_d2 = (const float*)d_in[13];
    float* out = (float*)d_out;
    const int* src = knn;
    const int* dst = knn + NEDGE;

    __half *p_h0, *p_agg0h, *p_h1, *p_agg1h;
    float *p_lat, *p_lat2, *p_base, *p_dinv;
    cudaGetSymbolAddress((void**)&p_h0,    g_h0);
    cudaGetSymbolAddress((void**)&p_agg0h, g_agg0h);
    cudaGetSymbolAddress((void**)&p_h1,    g_h1);
    cudaGetSymbolAddress((void**)&p_agg1h, g_agg1h);
    cudaGetSymbolAddress((void**)&p_lat,   g_lat);
    cudaGetSymbolAddress((void**)&p_lat2,  g_lat2);
    cudaGetSymbolAddress((void**)&p_base,  g_base);
    cudaGetSymbolAddress((void**)&p_dinv,  g_dinv);

    // zero split buffer 1 of each level (buffer 0 is seeded by producers)
    cudaMemsetAsync(p_agg0h + ROW0, 0, (size_t)ROW0 * sizeof(__half));
    cudaMemsetAsync(p_agg1h + ROW1, 0, (size_t)ROW1 * sizeof(__half));

    init_kernel<<<BN / 256, 256>>>();
    deg_kernel<<<NEDGE / 256, 256>>>(dst);
    dinv_kernel<<<BN / 256, 256>>>();
    cov_e1_kernel<<<BN / 32, 128>>>(x, w_e1, b_e1);

    // GCN layer 1: 64 halves/row = 8 chunks of 8 halves
    edge_kernel<3><<<(NEDGE * 8) / 256, 256>>>(src, dst, p_h0, p_agg0h, ROW0);
    gemm_tf32_kernel<C1, C0, false><<<dim3(C1 / 128, BN / 128), 256>>>(
        p_agg0h, ROW0, p_dinv, w_g1, b_g1, p_h1, p_agg1h, nullptr);

    // GCN layer 2 + fused max-pool: 128 halves/row = 16 chunks of 8 halves
    edge_kernel<4><<<(NEDGE * 16) / 256, 256>>>(src, dst, p_h1, p_agg1h, ROW1);
    gemm_tf32_kernel<C2, C1, true><<<dim3(C2 / 128, BN / 128), 256>>>(
        p_agg1h, ROW1, p_dinv, w_g2, b_g2, nullptr, nullptr, p_lat);

    e2_kernel<<<NB, C2>>>(p_lat, w_e2, b_e2, p_lat2);
    base_kernel<<<NB * 6, 32>>>(p_lat2, w_d1, w_d2, p_base);
    final_kernel<<<BN / 256, 256>>>(p_base, w_d1, b_d1, w_d2, b_d2, out);
}

// round 15
// speedup vs baseline: 1.3621x; 1.0015x over previous
#include <cuda_runtime.h>
#include <cuda_fp16.h>
#include <math.h>
#include <stdint.h>

#define NB    8
#define NPTS  4096
#define BN    32768
#define NEDGE 524288
#define C0    64
#define C1    128
#define C2    512
#define ROW0  (BN * C0)
#define ROW1  (BN * C1)

// ---------------- scratch ----------------
__device__ __half g_h0[ROW0];          // hs0 = dinv*h0 (fp16)
__device__ __half g_agg0h[2 * ROW0];   // 2 split accumulators, buffer0 seeded with hs0
__device__ __half g_h1[ROW1];
__device__ __half g_agg1h[2 * ROW1];
__device__ float  g_dinv[BN];
__device__ int    g_deg[BN];
__device__ float  g_lat[NB * C2];
__device__ float  g_lat2[NB * C2];
__device__ float  g_base[NB * 6];

__device__ __forceinline__ float selu_f(float v) {
    const float scale = 1.0507009873554805f;
    const float alpha = 1.6732632423543772f;
    return v > 0.0f ? scale * v : scale * alpha * expm1f(v);
}

__device__ __forceinline__ void atomicMaxF(float* addr, float v) {
    if (v >= 0.0f) atomicMax((int*)addr, __float_as_int(v));
    else           atomicMin((unsigned int*)addr, __float_as_uint(v));
}

__device__ __forceinline__ float f2tf32f(float v) {
    uint32_t r;
    asm("cvt.rna.tf32.f32 %0, %1;" : "=r"(r) : "f"(v));
    return __uint_as_float(r);
}

__device__ __forceinline__ uint32_t h2_bits(__half2 h) {
    uint32_t u;
    *reinterpret_cast<__half2*>(&u) = h;
    return u;
}
__device__ __forceinline__ __half2 bits_h2(uint32_t u) {
    return *reinterpret_cast<__half2*>(&u);
}

__device__ __forceinline__ uint4 ldg_nc_u4(const uint4* p) {
    uint4 v;
    asm volatile("ld.global.nc.v4.u32 {%0,%1,%2,%3}, [%4];"
                 : "=r"(v.x), "=r"(v.y), "=r"(v.z), "=r"(v.w) : "l"(p));
    return v;
}

__device__ __forceinline__ void red_add_v4h(__half* p, uint4 v) {
    asm volatile("red.global.add.noftz.v4.f16x2 [%0], {%1,%2,%3,%4};"
                 :: "l"(p), "r"(v.x), "r"(v.y), "r"(v.z), "r"(v.w) : "memory");
}

__device__ __forceinline__ void mma_tf32(float d[4],
                                         uint32_t a0, uint32_t a1, uint32_t a2, uint32_t a3,
                                         uint32_t b0, uint32_t b1) {
    asm volatile("mma.sync.aligned.m16n8k8.row.col.f32.tf32.tf32.f32 "
                 "{%0,%1,%2,%3},{%4,%5,%6,%7},{%8,%9},{%0,%1,%2,%3};"
                 : "+f"(d[0]), "+f"(d[1]), "+f"(d[2]), "+f"(d[3])
                 : "r"(a0), "r"(a1), "r"(a2), "r"(a3), "r"(b0), "r"(b1));
}

// ---------------- degree (deg pre-zeroed by memset; self loop folded into dinv) ----------------
__global__ void deg_kernel(const int* __restrict__ dst) {
    int e = blockIdx.x * blockDim.x + threadIdx.x;
    if (e < NEDGE) atomicAdd(&g_deg[dst[e]], 1);
}
// dinv + lat init fused
__global__ void dinv_kernel() {
    int i = blockIdx.x * blockDim.x + threadIdx.x;
    if (i < BN) g_dinv[i] = rsqrtf((float)(g_deg[i] + 1));
    if (i < NB * C2) g_lat[i] = __int_as_float(0xff800000);
}

// ---------------- cov + 12->64 + selu -> hs0 fp16 (writes h0 AND agg0h buffer0) ----------------
// 128 threads, 32 points per block. Phase 2 uses 64 threads (2 per point, shfl combine).
__global__ void __launch_bounds__(128)
cov_e1_kernel(const float* __restrict__ x,
              const float* __restrict__ w_e1,
              const float* __restrict__ b_e1) {
    __shared__ float xw[56][3];
    __shared__ float ws[12 * 64];
    __shared__ float bs[64];
    __shared__ float feat_s[32][13];
    __shared__ float out_s[32][68];
    int t = threadIdx.x;
    int blk = blockIdx.x;
    int b = blk >> 7;
    int n_base = (blk & 127) << 5;
    int point0 = blk << 5;

    if (t < 56) {
        int idx = n_base + t - 12;
        idx = min(max(idx, 0), NPTS - 1);
        const float* xp = x + (((size_t)b << 12) + idx) * 3;
        xw[t][0] = xp[0]; xw[t][1] = xp[1]; xw[t][2] = xp[2];
    }
    for (int i = t; i < 12 * 64; i += 128) ws[i] = w_e1[i];
    if (t < 64) bs[t] = b_e1[t];
    __syncthreads();

    if (t < 64) {
        int pt = t >> 1, half = t & 1;      // 2 threads per point
        int n = n_base + pt;
        int w0 = half * 13, w1 = half ? 25 : 13;   // half0: [0,13), half1: [13,25)
        float m0 = 0.f, m1 = 0.f, m2 = 0.f, cnt = 0.f;
        for (int w = w0; w < w1; w++) {
            int nn = n + w - 12;
            if (nn >= 0 && nn < NPTS) {
                m0 += xw[pt + w][0]; m1 += xw[pt + w][1]; m2 += xw[pt + w][2];
                cnt += 1.0f;
            }
        }
        m0  += __shfl_xor_sync(0xffffffffu, m0, 1);
        m1  += __shfl_xor_sync(0xffffffffu, m1, 1);
        m2  += __shfl_xor_sync(0xffffffffu, m2, 1);
        cnt += __shfl_xor_sync(0xffffffffu, cnt, 1);
        float ic = 1.0f / cnt;
        m0 *= ic; m1 *= ic; m2 *= ic;

        float c00=0,c01=0,c02=0,c11=0,c12=0,c22=0;
        for (int w = w0; w < w1; w++) {
            int nn = n + w - 12;
            if (nn >= 0 && nn < NPTS) {
                float d0 = xw[pt + w][0] - m0;
                float d1 = xw[pt + w][1] - m1;
                float d2 = xw[pt + w][2] - m2;
                c00 = fmaf(d0,d0,c00); c01 = fmaf(d0,d1,c01); c02 = fmaf(d0,d2,c02);
                c11 = fmaf(d1,d1,c11); c12 = fmaf(d1,d2,c12); c22 = fmaf(d2,d2,c22);
            }
        }
        c00 += __shfl_xor_sync(0xffffffffu, c00, 1);
        c01 += __shfl_xor_sync(0xffffffffu, c01, 1);
        c02 += __shfl_xor_sync(0xffffffffu, c02, 1);
        c11 += __shfl_xor_sync(0xffffffffu, c11, 1);
        c12 += __shfl_xor_sync(0xffffffffu, c12, 1);
        c22 += __shfl_xor_sync(0xffffffffu, c22, 1);

        const float s = 1.0f / 23.0f;
        if (half == 0) {
            feat_s[pt][0] = xw[pt + 12][0]; feat_s[pt][1] = xw[pt + 12][1]; feat_s[pt][2] = xw[pt + 12][2];
            feat_s[pt][3] = c00 * s; feat_s[pt][4] = c01 * s; feat_s[pt][5] = c02 * s;
        } else {
            feat_s[pt][6] = c01 * s; feat_s[pt][7]  = c11 * s; feat_s[pt][8]  = c12 * s;
            feat_s[pt][9] = c02 * s; feat_s[pt][10] = c12 * s; feat_s[pt][11] = c22 * s;
        }
    }
    __syncthreads();

    int pt = t >> 2, quarter = t & 3;     // 4 threads per point, 16 cols each
    float dv = g_dinv[point0 + pt];
    float feat[12];
    #pragma unroll
    for (int k = 0; k < 12; k++) feat[k] = feat_s[pt][k];
    #pragma unroll
    for (int jj = 0; jj < 16; jj++) {
        int j = (quarter << 4) + jj;
        float acc = bs[j];
        #pragma unroll
        for (int k = 0; k < 12; k++) acc = fmaf(feat[k], ws[k * 64 + j], acc);
        out_s[pt][j] = dv * selu_f(acc);
    }
    __syncthreads();

    for (int i = t; i < 256; i += 128) {
        int row = i >> 3, seg = i & 7;
        const float* src = &out_s[row][seg << 3];
        uint4 pk;
        pk.x = h2_bits(__floats2half2_rn(src[0], src[1]));
        pk.y = h2_bits(__floats2half2_rn(src[2], src[3]));
        pk.z = h2_bits(__floats2half2_rn(src[4], src[5]));
        pk.w = h2_bits(__floats2half2_rn(src[6], src[7]));
        size_t goff = (size_t)(point0 + row) * 64 + (seg << 3);
        *reinterpret_cast<uint4*>(g_h0 + goff)     = pk;
        *reinterpret_cast<uint4*>(g_agg0h + goff)  = pk;   // buffer 0 seed
    }
}

// ---------------- edge scatter fp16, 2-way split: agg[e&1][d] += hs[s] ----------------
template<int LOGC>
__global__ void edge_kernel(const int* __restrict__ src, const int* __restrict__ dst,
                            const __half* __restrict__ hs, __half* __restrict__ agg,
                            int bufstride) {
    int idx = blockIdx.x * blockDim.x + threadIdx.x;
    int e = idx >> LOGC;
    int g = idx & ((1 << LOGC) - 1);
    if (e >= NEDGE) return;
    int s = src[e], d = dst[e];
    int buf = e & 1;
    uint4 v = ldg_nc_u4(reinterpret_cast<const uint4*>(hs + ((size_t)s << (LOGC + 3))) + g);
    red_add_v4h(agg + (size_t)buf * bufstride + ((size_t)d << (LOGC + 3)) + (g << 3), v);
}

// ---------------- single-pass TF32 GEMM, 2-buffer fp16 A, 128x128 tile, double-buffered ----------------
template<int N, int K, bool DO_MAX>
__global__ void __launch_bounds__(256, 2)
gemm_tf32_kernel(const __half* __restrict__ A, int bufstride,
                 const float* __restrict__ dinv,
                 const float* __restrict__ Wt, const float* __restrict__ bias,
                 __half* __restrict__ O1, __half* __restrict__ Oseed,
                 float* __restrict__ lat) {
    __shared__ float Ah[2][128][20];
    __shared__ float Bh[2][16][132];

    int tid = threadIdx.x;
    int warp = tid >> 5, lane = tid & 31;
    int wm = warp >> 2, wn = warp & 3;
    int g = lane >> 2, c = lane & 3;
    int row0 = blockIdx.y * 128, col0 = blockIdx.x * 128;

    int ar = tid >> 1;
    int ak = (tid & 1) << 3;
    float dv = dinv[row0 + ar];
    int bkr = tid >> 4;
    int bc0 = (tid & 15) << 3;

    const int KT = K / 16;
    const uint4* A4 = reinterpret_cast<const uint4*>(A);
    int bs4 = bufstride >> 3;

    float d[4][4][4];
    #pragma unroll
    for (int mt = 0; mt < 4; mt++)
        #pragma unroll
        for (int nt = 0; nt < 4; nt++)
            #pragma unroll
            for (int r = 0; r < 4; r++) d[mt][nt][r] = 0.0f;

    auto load_a = [&](int koff, uint4 raw[2]) {
        size_t off = ((size_t)(row0 + ar) * K + koff + ak) >> 3;
        raw[0] = ldg_nc_u4(A4 + off);
        raw[1] = ldg_nc_u4(A4 + (size_t)bs4 + off);
    };
    auto stage_a = [&](int buf, uint4 raw[2]) {
        uint32_t w0[4] = {raw[0].x, raw[0].y, raw[0].z, raw[0].w};
        uint32_t w1[4] = {raw[1].x, raw[1].y, raw[1].z, raw[1].w};
        #pragma unroll
        for (int j = 0; j < 4; j++) {
            float2 f0 = __half22float2(bits_h2(w0[j]));
            float2 f1 = __half22float2(bits_h2(w1[j]));
            Ah[buf][ar][ak + 2 * j]     = f2tf32f(dv * (f0.x + f1.x));
            Ah[buf][ar][ak + 2 * j + 1] = f2tf32f(dv * (f0.y + f1.y));
        }
    };
    auto stage_b = [&](int buf, float4 b0, float4 b1) {
        Bh[buf][bkr][bc0 + 0] = f2tf32f(b0.x); Bh[buf][bkr][bc0 + 1] = f2tf32f(b0.y);
        Bh[buf][bkr][bc0 + 2] = f2tf32f(b0.z); Bh[buf][bkr][bc0 + 3] = f2tf32f(b0.w);
        Bh[buf][bkr][bc0 + 4] = f2tf32f(b1.x); Bh[buf][bkr][bc0 + 5] = f2tf32f(b1.y);
        Bh[buf][bkr][bc0 + 6] = f2tf32f(b1.z); Bh[buf][bkr][bc0 + 7] = f2tf32f(b1.w);
    };

    {
        uint4 raw[2];
        load_a(0, raw);
        stage_a(0, raw);
        float4 b0 = *reinterpret_cast<const float4*>(Wt + (size_t)bkr * N + col0 + bc0);
        float4 b1 = *reinterpret_cast<const float4*>(Wt + (size_t)bkr * N + col0 + bc0 + 4);
        stage_b(0, b0, b1);
    }
    __syncthreads();

    for (int kt = 0; kt < KT; kt++) {
        int cur = kt & 1, nxt = cur ^ 1;
        uint4 raw[2]; float4 b0, b1;
        bool more = (kt + 1 < KT);
        if (more) {
            int koff = (kt + 1) * 16;
            load_a(koff, raw);
            b0 = *reinterpret_cast<const float4*>(Wt + (size_t)(koff + bkr) * N + col0 + bc0);
            b1 = *reinterpret_cast<const float4*>(Wt + (size_t)(koff + bkr) * N + col0 + bc0 + 4);
        }

        #pragma unroll
        for (int ks = 0; ks < 2; ks++) {
            int k0 = ks << 3;
            uint32_t af[4][4];
            #pragma unroll
            for (int mt = 0; mt < 4; mt++) {
                int rm = wm * 64 + mt * 16;
                af[mt][0] = __float_as_uint(Ah[cur][rm + g][k0 + c]);
                af[mt][1] = __float_as_uint(Ah[cur][rm + g + 8][k0 + c]);
                af[mt][2] = __float_as_uint(Ah[cur][rm + g][k0 + c + 4]);
                af[mt][3] = __float_as_uint(Ah[cur][rm + g + 8][k0 + c + 4]);
            }
            uint32_t bf[4][2];
            #pragma unroll
            for (int nt = 0; nt < 4; nt++) {
                int nb = wn * 32 + nt * 8;
                bf[nt][0] = __float_as_uint(Bh[cur][k0 + c][nb + g]);
                bf[nt][1] = __float_as_uint(Bh[cur][k0 + c + 4][nb + g]);
            }
            #pragma unroll
            for (int mt = 0; mt < 4; mt++)
                #pragma unroll
                for (int nt = 0; nt < 4; nt++)
                    mma_tf32(d[mt][nt], af[mt][0], af[mt][1], af[mt][2], af[mt][3],
                             bf[nt][0], bf[nt][1]);
        }

        if (more) { stage_a(nxt, raw); stage_b(nxt, b0, b1); }
        __syncthreads();
    }

    float bv[4][2];
    #pragma unroll
    for (int nt = 0; nt < 4; nt++) {
        int cc = col0 + wn * 32 + nt * 8 + (c << 1);
        bv[nt][0] = bias[cc];
        bv[nt][1] = bias[cc + 1];
    }

    if (!DO_MAX) {
        #pragma unroll
        for (int mt = 0; mt < 4; mt++) {
            int rbase = row0 + wm * 64 + mt * 16;
            #pragma unroll
            for (int half = 0; half < 2; half++) {
                int r = rbase + g + half * 8;
                float dv2 = dinv[r];
                #pragma unroll
                for (int nt = 0; nt < 4; nt++) {
                    int cc = col0 + wn * 32 + nt * 8 + (c << 1);
                    __half2 o = __floats2half2_rn(
                        dv2 * selu_f(d[mt][nt][half * 2 + 0] + bv[nt][0]),
                        dv2 * selu_f(d[mt][nt][half * 2 + 1] + bv[nt][1]));
                    size_t addr = (size_t)r * N + cc;
                    *reinterpret_cast<__half2*>(O1 + addr)    = o;
                    *reinterpret_cast<__half2*>(Oseed + addr) = o;
                }
            }
        }
    } else {
        float mv[4][2];
        #pragma unroll
        for (int nt = 0; nt < 4; nt++) { mv[nt][0] = mv[nt][1] = __int_as_float(0xff800000); }
        #pragma unroll
        for (int mt = 0; mt < 4; mt++)
            #pragma unroll
            for (int nt = 0; nt < 4; nt++) {
                mv[nt][0] = fmaxf(mv[nt][0], fmaxf(selu_f(d[mt][nt][0] + bv[nt][0]),
                                                   selu_f(d[mt][nt][2] + bv[nt][0])));
                mv[nt][1] = fmaxf(mv[nt][1], fmaxf(selu_f(d[mt][nt][1] + bv[nt][1]),
                                                   selu_f(d[mt][nt][3] + bv[nt][1])));
            }
        #pragma unroll
        for (int off = 4; off <= 16; off <<= 1)
            #pragma unroll
            for (int nt = 0; nt < 4; nt++) {
                mv[nt][0] = fmaxf(mv[nt][0], __shfl_xor_sync(0xffffffffu, mv[nt][0], off));
                mv[nt][1] = fmaxf(mv[nt][1], __shfl_xor_sync(0xffffffffu, mv[nt][1], off));
            }
        if (lane < 4) {
            int b = row0 >> 12;
            #pragma unroll
            for (int nt = 0; nt < 4; nt++) {
                int cc = col0 + wn * 32 + nt * 8 + (lane << 1);
                atomicMaxF(&lat[b * C2 + cc], mv[nt][0]);
                atomicMaxF(&lat[b * C2 + cc + 1], mv[nt][1]);
            }
        }
    }
}

// ---------------- lat2 = selu(lat @ w_e2 + b_e2), regridded: (4 col-chunks x 8 batches) ----------------
__global__ void __launch_bounds__(128)
e2_kernel(const float* __restrict__ lat, const float* __restrict__ w,
          const float* __restrict__ bias, float* __restrict__ lat2) {
    __shared__ float row[C2];
    int b = blockIdx.y;
    int col0 = blockIdx.x * 128;
    int t = threadIdx.x;
    for (int k = t; k < C2; k += 128) row[k] = lat[b * C2 + k];
    __syncthreads();
    int c = col0 + t;
    float acc = bias[c];
    #pragma unroll 8
    for (int k = 0; k < C2; k++) acc = fmaf(row[k], w[k * C2 + c], acc);
    lat2[b * C2 + c] = selu_f(acc);
}

// ---------------- decoder ----------------
__global__ void base_kernel(const float* __restrict__ lat2,
                            const float* __restrict__ w_d1,
                            const float* __restrict__ w_d2,
                            float* __restrict__ base) {
    int o = blockIdx.x;
    int b = o / 6, t = o % 6, j = t % 3;
    const float* w = (t < 3) ? w_d1 : w_d2;
    int lane = threadIdx.x;
    float s = 0.0f;
    for (int c = lane; c < C2; c += 32) s += lat2[b * C2 + c] * w[c * 3 + j];
    #pragma unroll
    for (int off = 16; off > 0; off >>= 1) s += __shfl_xor_sync(0xffffffffu, s, off);
    if (lane == 0) base[b * 6 + t] = s;
}

__global__ void final_kernel(const float* __restrict__ base,
                             const float* __restrict__ w_d1, const float* __restrict__ b_d1,
                             const float* __restrict__ w_d2, const float* __restrict__ b_d2,
                             float* __restrict__ out) {
    int idx = blockIdx.x * blockDim.x + threadIdx.x;
    int b = idx >> 12, n = idx & 4095;
    int ix = n / 46, iy = n % 46;
    float y0 = 1.0f + ix * (119.0f / 90.0f);
    float y1 = 1.0f + iy * (59.0f / 45.0f);
    float kk[3];
    #pragma unroll
    for (int j = 0; j < 3; j++)
        kk[j] = selu_f(base[b * 6 + j] + y0 * w_d1[512 * 3 + j] + y1 * w_d1[513 * 3 + j] + b_d1[j]);
    #pragma unroll
    for (int j = 0; j < 3; j++) {
        float v = base[b * 6 + 3 + j]
                + kk[0] * w_d2[512 * 3 + j]
                + kk[1] * w_d2[513 * 3 + j]
                + kk[2] * w_d2[514 * 3 + j]
                + b_d2[j];
        out[(size_t)idx * 3 + j] = selu_f(v);
    }
}

// ---------------- launch ----------------
extern "C" void kernel_launch(void* const* d_in, const int* in_sizes, int n_in,
                              void* d_out, int out_size) {
    const float* x    = (const float*)d_in[0];
    const int*   knn  = (const int*)  d_in[1];
    const float* w_e1 = (const float*)d_in[2];
    const float* b_e1 = (const float*)d_in[3];
    const float* w_g1 = (const float*)d_in[4];
    const float* b_g1 = (const float*)d_in[5];
    const float* w_g2 = (const float*)d_in[6];
    const float* b_g2 = (const float*)d_in[7];
    const float* w_e2 = (const float*)d_in[8];
    const float* b_e2 = (const float*)d_in[9];
    const float* w_d1 = (const float*)d_in[10];
    const float* b_d1 = (const float*)d_in[11];
    const float* w_d2 = (const float*)d_in[12];
    const float* b_d2 = (const float*)d_in[13];
    float* out = (float*)d_out;
    const int* src = knn;
    const int* dst = knn + NEDGE;

    __half *p_h0, *p_agg0h, *p_h1, *p_agg1h;
    float *p_lat, *p_lat2, *p_base, *p_dinv;
    int* p_deg;
    cudaGetSymbolAddress((void**)&p_h0,    g_h0);
    cudaGetSymbolAddress((void**)&p_agg0h, g_agg0h);
    cudaGetSymbolAddress((void**)&p_h1,    g_h1);
    cudaGetSymbolAddress((void**)&p_agg1h, g_agg1h);
    cudaGetSymbolAddress((void**)&p_lat,   g_lat);
    cudaGetSymbolAddress((void**)&p_lat2,  g_lat2);
    cudaGetSymbolAddress((void**)&p_base,  g_base);
    cudaGetSymbolAddress((void**)&p_dinv,  g_dinv);
    cudaGetSymbolAddress((void**)&p_deg,   g_deg);

    // zero: deg, split buffer 1 of each level (buffer 0 seeded by producers)
    cudaMemsetAsync(p_deg, 0, BN * sizeof(int));
    cudaMemsetAsync(p_agg0h + ROW0, 0, (size_t)ROW0 * sizeof(__half));
    cudaMemsetAsync(p_agg1h + ROW1, 0, (size_t)ROW1 * sizeof(__half));

    deg_kernel<<<NEDGE / 256, 256>>>(dst);
    dinv_kernel<<<BN / 256, 256>>>();
    cov_e1_kernel<<<BN / 32, 128>>>(x, w_e1, b_e1);

    // GCN layer 1: 64 halves/row = 8 chunks of 8 halves
    edge_kernel<3><<<(NEDGE * 8) / 256, 256>>>(src, dst, p_h0, p_agg0h, ROW0);
    gemm_tf32_kernel<C1, C0, false><<<dim3(C1 / 128, BN / 128), 256>>>(
        p_agg0h, ROW0, p_dinv, w_g1, b_g1, p_h1, p_agg1h, nullptr);

    // GCN layer 2 + fused max-pool: 128 halves/row = 16 chunks of 8 halves
    edge_kernel<4><<<(NEDGE * 16) / 256, 256>>>(src, dst, p_h1, p_agg1h, ROW1);
    gemm_tf32_kernel<C2, C1, true><<<dim3(C2 / 128, BN / 128), 256>>>(
        p_agg1h, ROW1, p_dinv, w_g2, b_g2, nullptr, nullptr, p_lat);

    e2_kernel<<<dim3(C2 / 128, NB), 128>>>(p_lat, w_e2, b_e2, p_lat2);
    base_kernel<<<NB * 6, 32>>>(p_lat2, w_d1, w_d2, p_base);
    final_kernel<<<BN / 256, 256>>>(p_base, w_d1, b_d1, w_d2, b_d2, out);
}

// round 16
// speedup vs baseline: 1.3935x; 1.0230x over previous
#include <cuda_runtime.h>
#include <cuda_fp16.h>
#include <math.h>
#include <stdint.h>

#define NB    8
#define NPTS  4096
#define BN    32768
#define NEDGE 524288
#define C0    64
#define C1    128
#define C2    512
#define ROW0  (BN * C0)
#define ROW1  (BN * C1)

// ---------------- scratch ----------------
__device__ __half g_h0[ROW0];          // hs0 = dinv*h0 (fp16)
__device__ __half g_agg0h[2 * ROW0];   // 2 split accumulators, buffer0 seeded with hs0
__device__ __half g_h1[ROW1];
__device__ __half g_agg1h[2 * ROW1];
__device__ float  g_dinv[BN];
__device__ int    g_deg[BN];
__device__ float  g_lat[NB * C2];
__device__ float  g_lat2[NB * C2];

__device__ __forceinline__ float selu_f(float v) {
    const float scale = 1.0507009873554805f;
    const float alpha = 1.6732632423543772f;
    return v > 0.0f ? scale * v : scale * alpha * expm1f(v);
}

__device__ __forceinline__ void atomicMaxF(float* addr, float v) {
    if (v >= 0.0f) atomicMax((int*)addr, __float_as_int(v));
    else           atomicMin((unsigned int*)addr, __float_as_uint(v));
}

__device__ __forceinline__ float f2tf32f(float v) {
    uint32_t r;
    asm("cvt.rna.tf32.f32 %0, %1;" : "=r"(r) : "f"(v));
    return __uint_as_float(r);
}

__device__ __forceinline__ uint32_t h2_bits(__half2 h) {
    uint32_t u;
    *reinterpret_cast<__half2*>(&u) = h;
    return u;
}
__device__ __forceinline__ __half2 bits_h2(uint32_t u) {
    return *reinterpret_cast<__half2*>(&u);
}

__device__ __forceinline__ uint4 ldg_nc_u4(const uint4* p) {
    uint4 v;
    asm volatile("ld.global.nc.v4.u32 {%0,%1,%2,%3}, [%4];"
                 : "=r"(v.x), "=r"(v.y), "=r"(v.z), "=r"(v.w) : "l"(p));
    return v;
}

__device__ __forceinline__ void red_add_v4h(__half* p, uint4 v) {
    asm volatile("red.global.add.noftz.v4.f16x2 [%0], {%1,%2,%3,%4};"
                 :: "l"(p), "r"(v.x), "r"(v.y), "r"(v.z), "r"(v.w) : "memory");
}

__device__ __forceinline__ void mma_tf32(float d[4],
                                         uint32_t a0, uint32_t a1, uint32_t a2, uint32_t a3,
                                         uint32_t b0, uint32_t b1) {
    asm volatile("mma.sync.aligned.m16n8k8.row.col.f32.tf32.tf32.f32 "
                 "{%0,%1,%2,%3},{%4,%5,%6,%7},{%8,%9},{%0,%1,%2,%3};"
                 : "+f"(d[0]), "+f"(d[1]), "+f"(d[2]), "+f"(d[3])
                 : "r"(a0), "r"(a1), "r"(a2), "r"(a3), "r"(b0), "r"(b1));
}

// ---------------- degree + lat init fused (deg pre-zeroed by memset) ----------------
__global__ void deg_kernel(const int* __restrict__ dst) {
    int e = blockIdx.x * blockDim.x + threadIdx.x;
    if (e < NEDGE) atomicAdd(&g_deg[dst[e]], 1);
    if (e < NB * C2) g_lat[e] = __int_as_float(0xff800000);
}

// ---------------- cov + dinv + 12->64 + selu -> hs0 fp16 (writes h0, agg0h buf0, dinv) --------
// 128 threads, 32 points per block.
__global__ void __launch_bounds__(128)
cov_e1_kernel(const float* __restrict__ x,
              const float* __restrict__ w_e1,
              const float* __restrict__ b_e1) {
    __shared__ float xw[56][3];
    __shared__ float ws[12 * 64];
    __shared__ float bs[64];
    __shared__ float feat_s[32][13];
    __shared__ float dinv_s[32];
    __shared__ float out_s[32][68];
    int t = threadIdx.x;
    int blk = blockIdx.x;
    int b = blk >> 7;
    int n_base = (blk & 127) << 5;
    int point0 = blk << 5;

    if (t < 56) {
        int idx = n_base + t - 12;
        idx = min(max(idx, 0), NPTS - 1);
        const float* xp = x + (((size_t)b << 12) + idx) * 3;
        xw[t][0] = xp[0]; xw[t][1] = xp[1]; xw[t][2] = xp[2];
    }
    for (int i = t; i < 12 * 64; i += 128) ws[i] = w_e1[i];
    if (t < 64) bs[t] = b_e1[t];
    if (t >= 64 && t < 96) {
        int pt = t - 64;
        float dv = rsqrtf((float)(g_deg[point0 + pt] + 1));
        dinv_s[pt] = dv;
        g_dinv[point0 + pt] = dv;
    }
    __syncthreads();

    if (t < 64) {
        int pt = t >> 1, half = t & 1;      // 2 threads per point
        int n = n_base + pt;
        int w0 = half * 13, w1 = half ? 25 : 13;
        float m0 = 0.f, m1 = 0.f, m2 = 0.f, cnt = 0.f;
        for (int w = w0; w < w1; w++) {
            int nn = n + w - 12;
            if (nn >= 0 && nn < NPTS) {
                m0 += xw[pt + w][0]; m1 += xw[pt + w][1]; m2 += xw[pt + w][2];
                cnt += 1.0f;
            }
        }
        m0  += __shfl_xor_sync(0xffffffffu, m0, 1);
        m1  += __shfl_xor_sync(0xffffffffu, m1, 1);
        m2  += __shfl_xor_sync(0xffffffffu, m2, 1);
        cnt += __shfl_xor_sync(0xffffffffu, cnt, 1);
        float ic = 1.0f / cnt;
        m0 *= ic; m1 *= ic; m2 *= ic;

        float c00=0,c01=0,c02=0,c11=0,c12=0,c22=0;
        for (int w = w0; w < w1; w++) {
            int nn = n + w - 12;
            if (nn >= 0 && nn < NPTS) {
                float d0 = xw[pt + w][0] - m0;
                float d1 = xw[pt + w][1] - m1;
                float d2 = xw[pt + w][2] - m2;
                c00 = fmaf(d0,d0,c00); c01 = fmaf(d0,d1,c01); c02 = fmaf(d0,d2,c02);
                c11 = fmaf(d1,d1,c11); c12 = fmaf(d1,d2,c12); c22 = fmaf(d2,d2,c22);
            }
        }
        c00 += __shfl_xor_sync(0xffffffffu, c00, 1);
        c01 += __shfl_xor_sync(0xffffffffu, c01, 1);
        c02 += __shfl_xor_sync(0xffffffffu, c02, 1);
        c11 += __shfl_xor_sync(0xffffffffu, c11, 1);
        c12 += __shfl_xor_sync(0xffffffffu, c12, 1);
        c22 += __shfl_xor_sync(0xffffffffu, c22, 1);

        const float s = 1.0f / 23.0f;
        if (half == 0) {
            feat_s[pt][0] = xw[pt + 12][0]; feat_s[pt][1] = xw[pt + 12][1]; feat_s[pt][2] = xw[pt + 12][2];
            feat_s[pt][3] = c00 * s; feat_s[pt][4] = c01 * s; feat_s[pt][5] = c02 * s;
        } else {
            feat_s[pt][6] = c01 * s; feat_s[pt][7]  = c11 * s; feat_s[pt][8]  = c12 * s;
            feat_s[pt][9] = c02 * s; feat_s[pt][10] = c12 * s; feat_s[pt][11] = c22 * s;
        }
    }
    __syncthreads();

    int pt = t >> 2, quarter = t & 3;     // 4 threads per point, 16 cols each
    float dv = dinv_s[pt];
    float feat[12];
    #pragma unroll
    for (int k = 0; k < 12; k++) feat[k] = feat_s[pt][k];
    #pragma unroll
    for (int jj = 0; jj < 16; jj++) {
        int j = (quarter << 4) + jj;
        float acc = bs[j];
        #pragma unroll
        for (int k = 0; k < 12; k++) acc = fmaf(feat[k], ws[k * 64 + j], acc);
        out_s[pt][j] = dv * selu_f(acc);
    }
    __syncthreads();

    for (int i = t; i < 256; i += 128) {
        int row = i >> 3, seg = i & 7;
        const float* src = &out_s[row][seg << 3];
        uint4 pk;
        pk.x = h2_bits(__floats2half2_rn(src[0], src[1]));
        pk.y = h2_bits(__floats2half2_rn(src[2], src[3]));
        pk.z = h2_bits(__floats2half2_rn(src[4], src[5]));
        pk.w = h2_bits(__floats2half2_rn(src[6], src[7]));
        size_t goff = (size_t)(point0 + row) * 64 + (seg << 3);
        *reinterpret_cast<uint4*>(g_h0 + goff)     = pk;
        *reinterpret_cast<uint4*>(g_agg0h + goff)  = pk;   // buffer 0 seed
    }
}

// ---------------- edge scatter fp16, 2-way split: agg[e&1][d] += hs[s] ----------------
template<int LOGC>
__global__ void edge_kernel(const int* __restrict__ src, const int* __restrict__ dst,
                            const __half* __restrict__ hs, __half* __restrict__ agg,
                            int bufstride) {
    int idx = blockIdx.x * blockDim.x + threadIdx.x;
    int e = idx >> LOGC;
    int g = idx & ((1 << LOGC) - 1);
    if (e >= NEDGE) return;
    int s = src[e], d = dst[e];
    int buf = e & 1;
    uint4 v = ldg_nc_u4(reinterpret_cast<const uint4*>(hs + ((size_t)s << (LOGC + 3))) + g);
    red_add_v4h(agg + (size_t)buf * bufstride + ((size_t)d << (LOGC + 3)) + (g << 3), v);
}

// ---------------- single-pass TF32 GEMM, 2-buffer fp16 A, 128x128 tile, double-buffered ----------------
template<int N, int K, bool DO_MAX>
__global__ void __launch_bounds__(256, 2)
gemm_tf32_kernel(const __half* __restrict__ A, int bufstride,
                 const float* __restrict__ dinv,
                 const float* __restrict__ Wt, const float* __restrict__ bias,
                 __half* __restrict__ O1, __half* __restrict__ Oseed,
                 float* __restrict__ lat) {
    __shared__ float Ah[2][128][20];
    __shared__ float Bh[2][16][132];

    int tid = threadIdx.x;
    int warp = tid >> 5, lane = tid & 31;
    int wm = warp >> 2, wn = warp & 3;
    int g = lane >> 2, c = lane & 3;
    int row0 = blockIdx.y * 128, col0 = blockIdx.x * 128;

    int ar = tid >> 1;
    int ak = (tid & 1) << 3;
    float dv = dinv[row0 + ar];
    int bkr = tid >> 4;
    int bc0 = (tid & 15) << 3;

    const int KT = K / 16;
    const uint4* A4 = reinterpret_cast<const uint4*>(A);
    int bs4 = bufstride >> 3;

    float d[4][4][4];
    #pragma unroll
    for (int mt = 0; mt < 4; mt++)
        #pragma unroll
        for (int nt = 0; nt < 4; nt++)
            #pragma unroll
            for (int r = 0; r < 4; r++) d[mt][nt][r] = 0.0f;

    auto load_a = [&](int koff, uint4 raw[2]) {
        size_t off = ((size_t)(row0 + ar) * K + koff + ak) >> 3;
        raw[0] = ldg_nc_u4(A4 + off);
        raw[1] = ldg_nc_u4(A4 + (size_t)bs4 + off);
    };
    auto stage_a = [&](int buf, uint4 raw[2]) {
        uint32_t w0[4] = {raw[0].x, raw[0].y, raw[0].z, raw[0].w};
        uint32_t w1[4] = {raw[1].x, raw[1].y, raw[1].z, raw[1].w};
        #pragma unroll
        for (int j = 0; j < 4; j++) {
            float2 f0 = __half22float2(bits_h2(w0[j]));
            float2 f1 = __half22float2(bits_h2(w1[j]));
            Ah[buf][ar][ak + 2 * j]     = f2tf32f(dv * (f0.x + f1.x));
            Ah[buf][ar][ak + 2 * j + 1] = f2tf32f(dv * (f0.y + f1.y));
        }
    };
    auto stage_b = [&](int buf, float4 b0, float4 b1) {
        Bh[buf][bkr][bc0 + 0] = f2tf32f(b0.x); Bh[buf][bkr][bc0 + 1] = f2tf32f(b0.y);
        Bh[buf][bkr][bc0 + 2] = f2tf32f(b0.z); Bh[buf][bkr][bc0 + 3] = f2tf32f(b0.w);
        Bh[buf][bkr][bc0 + 4] = f2tf32f(b1.x); Bh[buf][bkr][bc0 + 5] = f2tf32f(b1.y);
        Bh[buf][bkr][bc0 + 6] = f2tf32f(b1.z); Bh[buf][bkr][bc0 + 7] = f2tf32f(b1.w);
    };

    {
        uint4 raw[2];
        load_a(0, raw);
        stage_a(0, raw);
        float4 b0 = *reinterpret_cast<const float4*>(Wt + (size_t)bkr * N + col0 + bc0);
        float4 b1 = *reinterpret_cast<const float4*>(Wt + (size_t)bkr * N + col0 + bc0 + 4);
        stage_b(0, b0, b1);
    }
    __syncthreads();

    for (int kt = 0; kt < KT; kt++) {
        int cur = kt & 1, nxt = cur ^ 1;
        uint4 raw[2]; float4 b0, b1;
        bool more = (kt + 1 < KT);
        if (more) {
            int koff = (kt + 1) * 16;
            load_a(koff, raw);
            b0 = *reinterpret_cast<const float4*>(Wt + (size_t)(koff + bkr) * N + col0 + bc0);
            b1 = *reinterpret_cast<const float4*>(Wt + (size_t)(koff + bkr) * N + col0 + bc0 + 4);
        }

        #pragma unroll
        for (int ks = 0; ks < 2; ks++) {
            int k0 = ks << 3;
            uint32_t af[4][4];
            #pragma unroll
            for (int mt = 0; mt < 4; mt++) {
                int rm = wm * 64 + mt * 16;
                af[mt][0] = __float_as_uint(Ah[cur][rm + g][k0 + c]);
                af[mt][1] = __float_as_uint(Ah[cur][rm + g + 8][k0 + c]);
                af[mt][2] = __float_as_uint(Ah[cur][rm + g][k0 + c + 4]);
                af[mt][3] = __float_as_uint(Ah[cur][rm + g + 8][k0 + c + 4]);
            }
            uint32_t bf[4][2];
            #pragma unroll
            for (int nt = 0; nt < 4; nt++) {
                int nb = wn * 32 + nt * 8;
                bf[nt][0] = __float_as_uint(Bh[cur][k0 + c][nb + g]);
                bf[nt][1] = __float_as_uint(Bh[cur][k0 + c + 4][nb + g]);
            }
            #pragma unroll
            for (int mt = 0; mt < 4; mt++)
                #pragma unroll
                for (int nt = 0; nt < 4; nt++)
                    mma_tf32(d[mt][nt], af[mt][0], af[mt][1], af[mt][2], af[mt][3],
                             bf[nt][0], bf[nt][1]);
        }

        if (more) { stage_a(nxt, raw); stage_b(nxt, b0, b1); }
        __syncthreads();
    }

    float bv[4][2];
    #pragma unroll
    for (int nt = 0; nt < 4; nt++) {
        int cc = col0 + wn * 32 + nt * 8 + (c << 1);
        bv[nt][0] = bias[cc];
        bv[nt][1] = bias[cc + 1];
    }

    if (!DO_MAX) {
        #pragma unroll
        for (int mt = 0; mt < 4; mt++) {
            int rbase = row0 + wm * 64 + mt * 16;
            #pragma unroll
            for (int half = 0; half < 2; half++) {
                int r = rbase + g + half * 8;
                float dv2 = dinv[r];
                #pragma unroll
                for (int nt = 0; nt < 4; nt++) {
                    int cc = col0 + wn * 32 + nt * 8 + (c << 1);
                    __half2 o = __floats2half2_rn(
                        dv2 * selu_f(d[mt][nt][half * 2 + 0] + bv[nt][0]),
                        dv2 * selu_f(d[mt][nt][half * 2 + 1] + bv[nt][1]));
                    size_t addr = (size_t)r * N + cc;
                    *reinterpret_cast<__half2*>(O1 + addr)    = o;
                    *reinterpret_cast<__half2*>(Oseed + addr) = o;
                }
            }
        }
    } else {
        float mv[4][2];
        #pragma unroll
        for (int nt = 0; nt < 4; nt++) { mv[nt][0] = mv[nt][1] = __int_as_float(0xff800000); }
        #pragma unroll
        for (int mt = 0; mt < 4; mt++)
            #pragma unroll
            for (int nt = 0; nt < 4; nt++) {
                mv[nt][0] = fmaxf(mv[nt][0], fmaxf(selu_f(d[mt][nt][0] + bv[nt][0]),
                                                   selu_f(d[mt][nt][2] + bv[nt][0])));
                mv[nt][1] = fmaxf(mv[nt][1], fmaxf(selu_f(d[mt][nt][1] + bv[nt][1]),
                                                   selu_f(d[mt][nt][3] + bv[nt][1])));
            }
        #pragma unroll
        for (int off = 4; off <= 16; off <<= 1)
            #pragma unroll
            for (int nt = 0; nt < 4; nt++) {
                mv[nt][0] = fmaxf(mv[nt][0], __shfl_xor_sync(0xffffffffu, mv[nt][0], off));
                mv[nt][1] = fmaxf(mv[nt][1], __shfl_xor_sync(0xffffffffu, mv[nt][1], off));
            }
        if (lane < 4) {
            int b = row0 >> 12;
            #pragma unroll
            for (int nt = 0; nt < 4; nt++) {
                int cc = col0 + wn * 32 + nt * 8 + (lane << 1);
                atomicMaxF(&lat[b * C2 + cc], mv[nt][0]);
                atomicMaxF(&lat[b * C2 + cc + 1], mv[nt][1]);
            }
        }
    }
}

// ---------------- lat2 = selu(lat @ w_e2 + b_e2), (4 col-chunks x 8 batches) ----------------
__global__ void __launch_bounds__(128)
e2_kernel(const float* __restrict__ lat, const float* __restrict__ w,
          const float* __restrict__ bias, float* __restrict__ lat2) {
    __shared__ float row[C2];
    int b = blockIdx.y;
    int col0 = blockIdx.x * 128;
    int t = threadIdx.x;
    for (int k = t; k < C2; k += 128) row[k] = lat[b * C2 + k];
    __syncthreads();
    int c = col0 + t;
    float acc = bias[c];
    #pragma unroll 8
    for (int k = 0; k < C2; k++) acc = fmaf(row[k], w[k * C2 + c], acc);
    lat2[b * C2 + c] = selu_f(acc);
}

// ---------------- final: per-block base dots (warps 0-5) + closed-form folding ----------------
__global__ void __launch_bounds__(256)
final_kernel(const float* __restrict__ lat2,
             const float* __restrict__ w_d1, const float* __restrict__ b_d1,
             const float* __restrict__ w_d2, const float* __restrict__ b_d2,
             float* __restrict__ out) {
    __shared__ float l2s[C2];
    __shared__ float base_s[6];
    int t = threadIdx.x;
    int blk = blockIdx.x;                 // 128 blocks, 16 per batch
    int b = blk >> 4;
    int idx0 = blk << 8;                  // 256 points per block

    for (int k = t; k < C2; k += 256) l2s[k] = lat2[b * C2 + k];
    __syncthreads();

    int warp = t >> 5, lane = t & 31;
    if (warp < 6) {
        int j = warp % 3;
        const float* w = (warp < 3) ? w_d1 : w_d2;
        float s = 0.0f;
        for (int c = lane; c < C2; c += 32) s += l2s[c] * w[c * 3 + j];
        #pragma unroll
        for (int off = 16; off > 0; off >>= 1) s += __shfl_xor_sync(0xffffffffu, s, off);
        if (lane == 0) base_s[warp] = s;
    }
    __syncthreads();

    int idx = idx0 + t;
    int n = idx & 4095;
    int ix = n / 46, iy = n % 46;
    float y0 = 1.0f + ix * (119.0f / 90.0f);
    float y1 = 1.0f + iy * (59.0f / 45.0f);
    float kk[3];
    #pragma unroll
    for (int j = 0; j < 3; j++)
        kk[j] = selu_f(base_s[j] + y0 * w_d1[512 * 3 + j] + y1 * w_d1[513 * 3 + j] + b_d1[j]);
    #pragma unroll
    for (int j = 0; j < 3; j++) {
        float v = base_s[3 + j]
                + kk[0] * w_d2[512 * 3 + j]
                + kk[1] * w_d2[513 * 3 + j]
                + kk[2] * w_d2[514 * 3 + j]
                + b_d2[j];
        out[(size_t)idx * 3 + j] = selu_f(v);
    }
}

// ---------------- launch ----------------
extern "C" void kernel_launch(void* const* d_in, const int* in_sizes, int n_in,
                              void* d_out, int out_size) {
    const float* x    = (const float*)d_in[0];
    const int*   knn  = (const int*)  d_in[1];
    const float* w_e1 = (const float*)d_in[2];
    const float* b_e1 = (const float*)d_in[3];
    const float* w_g1 = (const float*)d_in[4];
    const float* b_g1 = (const float*)d_in[5];
    const float* w_g2 = (const float*)d_in[6];
    const float* b_g2 = (const float*)d_in[7];
    const float* w_e2 = (const float*)d_in[8];
    const float* b_e2 = (const float*)d_in[9];
    const float* w_d1 = (const float*)d_in[10];
    const float* b_d1 = (const float*)d_in[11];
    const float* w_d2 = (const float*)d_in[12];
    const float* b_d2 = (const float*)d_in[13];
    float* out = (float*)d_out;
    const int* src = knn;
    const int* dst = knn + NEDGE;

    __half *p_h0, *p_agg0h, *p_h1, *p_agg1h;
    float *p_lat, *p_lat2, *p_dinv;
    int* p_deg;
    cudaGetSymbolAddress((void**)&p_h0,    g_h0);
    cudaGetSymbolAddress((void**)&p_agg0h, g_agg0h);
    cudaGetSymbolAddress((void**)&p_h1,    g_h1);
    cudaGetSymbolAddress((void**)&p_agg1h, g_agg1h);
    cudaGetSymbolAddress((void**)&p_lat,   g_lat);
    cudaGetSymbolAddress((void**)&p_lat2,  g_lat2);
    cudaGetSymbolAddress((void**)&p_dinv,  g_dinv);
    cudaGetSymbolAddress((void**)&p_deg,   g_deg);

    cudaMemsetAsync(p_deg, 0, BN * sizeof(int));
    cudaMemsetAsync(p_agg0h + ROW0, 0, (size_t)ROW0 * sizeof(__half));
    cudaMemsetAsync(p_agg1h + ROW1, 0, (size_t)ROW1 * sizeof(__half));

    deg_kernel<<<NEDGE / 256, 256>>>(dst);
    cov_e1_kernel<<<BN / 32, 128>>>(x, w_e1, b_e1);

    // GCN layer 1: 64 halves/row = 8 chunks of 8 halves
    edge_kernel<3><<<(NEDGE * 8) / 256, 256>>>(src, dst, p_h0, p_agg0h, ROW0);
    gemm_tf32_kernel<C1, C0, false><<<dim3(C1 / 128, BN / 128), 256>>>(
        p_agg0h, ROW0, p_dinv, w_g1, b_g1, p_h1, p_agg1h, nullptr);

    // GCN layer 2 + fused max-pool: 128 halves/row = 16 chunks of 8 halves
    edge_kernel<4><<<(NEDGE * 16) / 256, 256>>>(src, dst, p_h1, p_agg1h, ROW1);
    gemm_tf32_kernel<C2, C1, true><<<dim3(C2 / 128, BN / 128), 256>>>(
        p_agg1h, ROW1, p_dinv, w_g2, b_g2, nullptr, nullptr, p_lat);

    e2_kernel<<<dim3(C2 / 128, NB), 128>>>(p_lat, w_e2, b_e2, p_lat2);
    final_kernel<<<BN / 256, 256>>>(p_lat2, w_d1, b_d1, w_d2, b_d2, out);
}

// round 17
// speedup vs baseline: 1.5107x; 1.0841x over previous
#include <cuda_runtime.h>
#include <cuda_fp16.h>
#include <math.h>
#include <stdint.h>

#define NB    8
#define NPTS  4096
#define BN    32768
#define NEDGE 524288
#define C0    64
#define C1    128
#define C2    512
#define ROW0  (BN * C0)
#define ROW1  (BN * C1)

// ---------------- scratch ----------------
__device__ __half g_h0[ROW0];          // hs0 = dinv*h0 (fp16)
__device__ __half g_agg0h[2 * ROW0];   // 2 split accumulators, buffer0 seeded with hs0
__device__ __half g_h1[ROW1];
__device__ __half g_agg1h[2 * ROW1];
__device__ float  g_dinv[BN];
__device__ int    g_deg[BN];
__device__ float  g_lat[NB * C2];
__device__ float  g_lat2[NB * C2];

__device__ __forceinline__ float selu_f(float v) {
    const float scale = 1.0507009873554805f;
    const float alpha = 1.6732632423543772f;
    return v > 0.0f ? scale * v : scale * alpha * expm1f(v);
}

__device__ __forceinline__ void atomicMaxF(float* addr, float v) {
    if (v >= 0.0f) atomicMax((int*)addr, __float_as_int(v));
    else           atomicMin((unsigned int*)addr, __float_as_uint(v));
}

__device__ __forceinline__ uint32_t h2_bits(__half2 h) {
    uint32_t u;
    *reinterpret_cast<__half2*>(&u) = h;
    return u;
}
__device__ __forceinline__ __half2 bits_h2(uint32_t u) {
    return *reinterpret_cast<__half2*>(&u);
}

__device__ __forceinline__ uint4 ldg_nc_u4(const uint4* p) {
    uint4 v;
    asm volatile("ld.global.nc.v4.u32 {%0,%1,%2,%3}, [%4];"
                 : "=r"(v.x), "=r"(v.y), "=r"(v.z), "=r"(v.w) : "l"(p));
    return v;
}

__device__ __forceinline__ void red_add_v4h(__half* p, uint4 v) {
    asm volatile("red.global.add.noftz.v4.f16x2 [%0], {%1,%2,%3,%4};"
                 :: "l"(p), "r"(v.x), "r"(v.y), "r"(v.z), "r"(v.w) : "memory");
}

// fp16 MMA m16n8k16, f32 accumulate
__device__ __forceinline__ void mma_f16(float d[4], const uint32_t a[4], const uint32_t b[2]) {
    asm volatile("mma.sync.aligned.m16n8k16.row.col.f32.f16.f16.f32 "
                 "{%0,%1,%2,%3},{%4,%5,%6,%7},{%8,%9},{%0,%1,%2,%3};"
                 : "+f"(d[0]), "+f"(d[1]), "+f"(d[2]), "+f"(d[3])
                 : "r"(a[0]), "r"(a[1]), "r"(a[2]), "r"(a[3]), "r"(b[0]), "r"(b[1]));
}

// ---------------- degree + lat init fused (deg pre-zeroed by memset) ----------------
__global__ void deg_kernel(const int* __restrict__ dst) {
    int e = blockIdx.x * blockDim.x + threadIdx.x;
    if (e < NEDGE) atomicAdd(&g_deg[dst[e]], 1);
    if (e < NB * C2) g_lat[e] = __int_as_float(0xff800000);
}

// ---------------- cov + dinv + 12->64 + selu -> hs0 fp16 ----------------
__global__ void __launch_bounds__(128)
cov_e1_kernel(const float* __restrict__ x,
              const float* __restrict__ w_e1,
              const float* __restrict__ b_e1) {
    __shared__ float xw[56][3];
    __shared__ float ws[12 * 64];
    __shared__ float bs[64];
    __shared__ float feat_s[32][13];
    __shared__ float dinv_s[32];
    __shared__ float out_s[32][68];
    int t = threadIdx.x;
    int blk = blockIdx.x;
    int b = blk >> 7;
    int n_base = (blk & 127) << 5;
    int point0 = blk << 5;

    if (t < 56) {
        int idx = n_base + t - 12;
        idx = min(max(idx, 0), NPTS - 1);
        const float* xp = x + (((size_t)b << 12) + idx) * 3;
        xw[t][0] = xp[0]; xw[t][1] = xp[1]; xw[t][2] = xp[2];
    }
    for (int i = t; i < 12 * 64; i += 128) ws[i] = w_e1[i];
    if (t < 64) bs[t] = b_e1[t];
    if (t >= 64 && t < 96) {
        int pt = t - 64;
        float dv = rsqrtf((float)(g_deg[point0 + pt] + 1));
        dinv_s[pt] = dv;
        g_dinv[point0 + pt] = dv;
    }
    __syncthreads();

    if (t < 64) {
        int pt = t >> 1, half = t & 1;
        int n = n_base + pt;
        int w0 = half * 13, w1 = half ? 25 : 13;
        float m0 = 0.f, m1 = 0.f, m2 = 0.f, cnt = 0.f;
        for (int w = w0; w < w1; w++) {
            int nn = n + w - 12;
            if (nn >= 0 && nn < NPTS) {
                m0 += xw[pt + w][0]; m1 += xw[pt + w][1]; m2 += xw[pt + w][2];
                cnt += 1.0f;
            }
        }
        m0  += __shfl_xor_sync(0xffffffffu, m0, 1);
        m1  += __shfl_xor_sync(0xffffffffu, m1, 1);
        m2  += __shfl_xor_sync(0xffffffffu, m2, 1);
        cnt += __shfl_xor_sync(0xffffffffu, cnt, 1);
        float ic = 1.0f / cnt;
        m0 *= ic; m1 *= ic; m2 *= ic;

        float c00=0,c01=0,c02=0,c11=0,c12=0,c22=0;
        for (int w = w0; w < w1; w++) {
            int nn = n + w - 12;
            if (nn >= 0 && nn < NPTS) {
                float d0 = xw[pt + w][0] - m0;
                float d1 = xw[pt + w][1] - m1;
                float d2 = xw[pt + w][2] - m2;
                c00 = fmaf(d0,d0,c00); c01 = fmaf(d0,d1,c01); c02 = fmaf(d0,d2,c02);
                c11 = fmaf(d1,d1,c11); c12 = fmaf(d1,d2,c12); c22 = fmaf(d2,d2,c22);
            }
        }
        c00 += __shfl_xor_sync(0xffffffffu, c00, 1);
        c01 += __shfl_xor_sync(0xffffffffu, c01, 1);
        c02 += __shfl_xor_sync(0xffffffffu, c02, 1);
        c11 += __shfl_xor_sync(0xffffffffu, c11, 1);
        c12 += __shfl_xor_sync(0xffffffffu, c12, 1);
        c22 += __shfl_xor_sync(0xffffffffu, c22, 1);

        const float s = 1.0f / 23.0f;
        if (half == 0) {
            feat_s[pt][0] = xw[pt + 12][0]; feat_s[pt][1] = xw[pt + 12][1]; feat_s[pt][2] = xw[pt + 12][2];
            feat_s[pt][3] = c00 * s; feat_s[pt][4] = c01 * s; feat_s[pt][5] = c02 * s;
        } else {
            feat_s[pt][6] = c01 * s; feat_s[pt][7]  = c11 * s; feat_s[pt][8]  = c12 * s;
            feat_s[pt][9] = c02 * s; feat_s[pt][10] = c12 * s; feat_s[pt][11] = c22 * s;
        }
    }
    __syncthreads();

    int pt = t >> 2, quarter = t & 3;
    float dv = dinv_s[pt];
    float feat[12];
    #pragma unroll
    for (int k = 0; k < 12; k++) feat[k] = feat_s[pt][k];
    #pragma unroll
    for (int jj = 0; jj < 16; jj++) {
        int j = (quarter << 4) + jj;
        float acc = bs[j];
        #pragma unroll
        for (int k = 0; k < 12; k++) acc = fmaf(feat[k], ws[k * 64 + j], acc);
        out_s[pt][j] = dv * selu_f(acc);
    }
    __syncthreads();

    for (int i = t; i < 256; i += 128) {
        int row = i >> 3, seg = i & 7;
        const float* src = &out_s[row][seg << 3];
        uint4 pk;
        pk.x = h2_bits(__floats2half2_rn(src[0], src[1]));
        pk.y = h2_bits(__floats2half2_rn(src[2], src[3]));
        pk.z = h2_bits(__floats2half2_rn(src[4], src[5]));
        pk.w = h2_bits(__floats2half2_rn(src[6], src[7]));
        size_t goff = (size_t)(point0 + row) * 64 + (seg << 3);
        *reinterpret_cast<uint4*>(g_h0 + goff)     = pk;
        *reinterpret_cast<uint4*>(g_agg0h + goff)  = pk;
    }
}

// ---------------- edge scatter fp16, 2-way split: agg[e&1][d] += hs[s] ----------------
template<int LOGC>
__global__ void edge_kernel(const int* __restrict__ src, const int* __restrict__ dst,
                            const __half* __restrict__ hs, __half* __restrict__ agg,
                            int bufstride) {
    int idx = blockIdx.x * blockDim.x + threadIdx.x;
    int e = idx >> LOGC;
    int g = idx & ((1 << LOGC) - 1);
    if (e >= NEDGE) return;
    int s = src[e], d = dst[e];
    int buf = e & 1;
    uint4 v = ldg_nc_u4(reinterpret_cast<const uint4*>(hs + ((size_t)s << (LOGC + 3))) + g);
    red_add_v4h(agg + (size_t)buf * bufstride + ((size_t)d << (LOGC + 3)) + (g << 3), v);
}

// ---------------- fp16 MMA GEMM, 2-buffer fp16 A, 128x128 tile, double-buffered ----------------
// A_eff[row] = fp16(dinv[row] * (A0[row] + A1[row]));  out = selu(A_eff @ fp16(W) + bias)
// mma m16n8k16; warp tile 64x32 (4 mt x 4 nt); 8 warps.
template<int N, int K, bool DO_MAX>
__global__ void __launch_bounds__(256, 2)
gemm_f16_kernel(const __half* __restrict__ A, int bufstride,
                const float* __restrict__ dinv,
                const float* __restrict__ Wt, const float* __restrict__ bias,
                __half* __restrict__ O1, __half* __restrict__ Oseed,
                float* __restrict__ lat) {
    __shared__ __half Ah[2][128][24];   // [row][k halves], 48B row stride
    __shared__ __half Bh[2][128][24];   // [col][k halves], 48B col stride

    int tid = threadIdx.x;
    int warp = tid >> 5, lane = tid & 31;
    int wm = warp >> 2, wn = warp & 3;
    int g = lane >> 2, c = lane & 3;
    int row0 = blockIdx.y * 128, col0 = blockIdx.x * 128;

    // A loader: thread -> (row, 8-half chunk)
    int ar = tid >> 1;
    int ak = (tid & 1) << 3;
    float dv = dinv[row0 + ar];
    // B loader: thread -> (col, 8-k chunk); coalesced scalar f32 loads per k row
    int bcol = tid & 127;
    int bk0 = (tid >> 7) << 3;

    const int KT = K / 16;
    const uint4* A4 = reinterpret_cast<const uint4*>(A);
    int bs4 = bufstride >> 3;

    float d[4][4][4];
    #pragma unroll
    for (int mt = 0; mt < 4; mt++)
        #pragma unroll
        for (int nt = 0; nt < 4; nt++)
            #pragma unroll
            for (int r = 0; r < 4; r++) d[mt][nt][r] = 0.0f;

    auto load_a = [&](int koff, uint4 raw[2]) {
        size_t off = ((size_t)(row0 + ar) * K + koff + ak) >> 3;
        raw[0] = ldg_nc_u4(A4 + off);
        raw[1] = ldg_nc_u4(A4 + (size_t)bs4 + off);
    };
    auto load_b = [&](int koff, float wv[8]) {
        #pragma unroll
        for (int j = 0; j < 8; j++)
            wv[j] = Wt[(size_t)(koff + bk0 + j) * N + col0 + bcol];
    };
    auto stage_a = [&](int buf, uint4 raw[2]) {
        uint32_t w0[4] = {raw[0].x, raw[0].y, raw[0].z, raw[0].w};
        uint32_t w1[4] = {raw[1].x, raw[1].y, raw[1].z, raw[1].w};
        uint4 pk;
        uint32_t* pkw = reinterpret_cast<uint32_t*>(&pk);
        #pragma unroll
        for (int j = 0; j < 4; j++) {
            float2 f0 = __half22float2(bits_h2(w0[j]));
            float2 f1 = __half22float2(bits_h2(w1[j]));
            pkw[j] = h2_bits(__floats2half2_rn(dv * (f0.x + f1.x), dv * (f0.y + f1.y)));
        }
        *reinterpret_cast<uint4*>(&Ah[buf][ar][ak]) = pk;
    };
    auto stage_b = [&](int buf, float wv[8]) {
        uint4 pk;
        uint32_t* pkw = reinterpret_cast<uint32_t*>(&pk);
        #pragma unroll
        for (int j = 0; j < 4; j++)
            pkw[j] = h2_bits(__floats2half2_rn(wv[2 * j], wv[2 * j + 1]));
        *reinterpret_cast<uint4*>(&Bh[buf][bcol][bk0]) = pk;
    };

    {
        uint4 raw[2]; float wv[8];
        load_a(0, raw); load_b(0, wv);
        stage_a(0, raw); stage_b(0, wv);
    }
    __syncthreads();

    for (int kt = 0; kt < KT; kt++) {
        int cur = kt & 1, nxt = cur ^ 1;
        uint4 raw[2]; float wv[8];
        bool more = (kt + 1 < KT);
        if (more) {
            int koff = (kt + 1) * 16;
            load_a(koff, raw);
            load_b(koff, wv);
        }

        uint32_t af[4][4];
        #pragma unroll
        for (int mt = 0; mt < 4; mt++) {
            int rm = wm * 64 + mt * 16;
            af[mt][0] = *reinterpret_cast<const uint32_t*>(&Ah[cur][rm + g][2 * c]);
            af[mt][1] = *reinterpret_cast<const uint32_t*>(&Ah[cur][rm + g + 8][2 * c]);
            af[mt][2] = *reinterpret_cast<const uint32_t*>(&Ah[cur][rm + g][2 * c + 8]);
            af[mt][3] = *reinterpret_cast<const uint32_t*>(&Ah[cur][rm + g + 8][2 * c + 8]);
        }
        uint32_t bf[4][2];
        #pragma unroll
        for (int nt = 0; nt < 4; nt++) {
            int nb = wn * 32 + nt * 8;
            bf[nt][0] = *reinterpret_cast<const uint32_t*>(&Bh[cur][nb + g][2 * c]);
            bf[nt][1] = *reinterpret_cast<const uint32_t*>(&Bh[cur][nb + g][2 * c + 8]);
        }
        #pragma unroll
        for (int mt = 0; mt < 4; mt++)
            #pragma unroll
            for (int nt = 0; nt < 4; nt++)
                mma_f16(d[mt][nt], af[mt], bf[nt]);

        if (more) { stage_a(nxt, raw); stage_b(nxt, wv); }
        __syncthreads();
    }

    float bv[4][2];
    #pragma unroll
    for (int nt = 0; nt < 4; nt++) {
        int cc = col0 + wn * 32 + nt * 8 + (c << 1);
        bv[nt][0] = bias[cc];
        bv[nt][1] = bias[cc + 1];
    }

    if (!DO_MAX) {
        #pragma unroll
        for (int mt = 0; mt < 4; mt++) {
            int rbase = row0 + wm * 64 + mt * 16;
            #pragma unroll
            for (int half = 0; half < 2; half++) {
                int r = rbase + g + half * 8;
                float dv2 = dinv[r];
                #pragma unroll
                for (int nt = 0; nt < 4; nt++) {
                    int cc = col0 + wn * 32 + nt * 8 + (c << 1);
                    __half2 o = __floats2half2_rn(
                        dv2 * selu_f(d[mt][nt][half * 2 + 0] + bv[nt][0]),
                        dv2 * selu_f(d[mt][nt][half * 2 + 1] + bv[nt][1]));
                    size_t addr = (size_t)r * N + cc;
                    *reinterpret_cast<__half2*>(O1 + addr)    = o;
                    *reinterpret_cast<__half2*>(Oseed + addr) = o;
                }
            }
        }
    } else {
        float mv[4][2];
        #pragma unroll
        for (int nt = 0; nt < 4; nt++) { mv[nt][0] = mv[nt][1] = __int_as_float(0xff800000); }
        #pragma unroll
        for (int mt = 0; mt < 4; mt++)
            #pragma unroll
            for (int nt = 0; nt < 4; nt++) {
                mv[nt][0] = fmaxf(mv[nt][0], fmaxf(selu_f(d[mt][nt][0] + bv[nt][0]),
                                                   selu_f(d[mt][nt][2] + bv[nt][0])));
                mv[nt][1] = fmaxf(mv[nt][1], fmaxf(selu_f(d[mt][nt][1] + bv[nt][1]),
                                                   selu_f(d[mt][nt][3] + bv[nt][1])));
            }
        #pragma unroll
        for (int off = 4; off <= 16; off <<= 1)
            #pragma unroll
            for (int nt = 0; nt < 4; nt++) {
                mv[nt][0] = fmaxf(mv[nt][0], __shfl_xor_sync(0xffffffffu, mv[nt][0], off));
                mv[nt][1] = fmaxf(mv[nt][1], __shfl_xor_sync(0xffffffffu, mv[nt][1], off));
            }
        if (lane < 4) {
            int b = row0 >> 12;
            #pragma unroll
            for (int nt = 0; nt < 4; nt++) {
                int cc = col0 + wn * 32 + nt * 8 + (lane << 1);
                atomicMaxF(&lat[b * C2 + cc], mv[nt][0]);
                atomicMaxF(&lat[b * C2 + cc + 1], mv[nt][1]);
            }
        }
    }
}

// ---------------- lat2 = selu(lat @ w_e2 + b_e2) ----------------
__global__ void __launch_bounds__(128)
e2_kernel(const float* __restrict__ lat, const float* __restrict__ w,
          const float* __restrict__ bias, float* __restrict__ lat2) {
    __shared__ float row[C2];
    int b = blockIdx.y;
    int col0 = blockIdx.x * 128;
    int t = threadIdx.x;
    for (int k = t; k < C2; k += 128) row[k] = lat[b * C2 + k];
    __syncthreads();
    int c = col0 + t;
    float acc = bias[c];
    #pragma unroll 8
    for (int k = 0; k < C2; k++) acc = fmaf(row[k], w[k * C2 + c], acc);
    lat2[b * C2 + c] = selu_f(acc);
}

// ---------------- final: per-block base dots + closed-form folding ----------------
__global__ void __launch_bounds__(256)
final_kernel(const float* __restrict__ lat2,
             const float* __restrict__ w_d1, const float* __restrict__ b_d1,
             const float* __restrict__ w_d2, const float* __restrict__ b_d2,
             float* __restrict__ out) {
    __shared__ float l2s[C2];
    __shared__ float base_s[6];
    int t = threadIdx.x;
    int blk = blockIdx.x;
    int b = blk >> 4;
    int idx0 = blk << 8;

    for (int k = t; k < C2; k += 256) l2s[k] = lat2[b * C2 + k];
    __syncthreads();

    int warp = t >> 5, lane = t & 31;
    if (warp < 6) {
        int j = warp % 3;
        const float* w = (warp < 3) ? w_d1 : w_d2;
        float s = 0.0f;
        for (int c = lane; c < C2; c += 32) s += l2s[c] * w[c * 3 + j];
        #pragma unroll
        for (int off = 16; off > 0; off >>= 1) s += __shfl_xor_sync(0xffffffffu, s, off);
        if (lane == 0) base_s[warp] = s;
    }
    __syncthreads();

    int idx = idx0 + t;
    int n = idx & 4095;
    int ix = n / 46, iy = n % 46;
    float y0 = 1.0f + ix * (119.0f / 90.0f);
    float y1 = 1.0f + iy * (59.0f / 45.0f);
    float kk[3];
    #pragma unroll
    for (int j = 0; j < 3; j++)
        kk[j] = selu_f(base_s[j] + y0 * w_d1[512 * 3 + j] + y1 * w_d1[513 * 3 + j] + b_d1[j]);
    #pragma unroll
    for (int j = 0; j < 3; j++) {
        float v = base_s[3 + j]
                + kk[0] * w_d2[512 * 3 + j]
                + kk[1] * w_d2[513 * 3 + j]
                + kk[2] * w_d2[514 * 3 + j]
                + b_d2[j];
        out[(size_t)idx * 3 + j] = selu_f(v);
    }
}

// ---------------- launch ----------------
extern "C" void kernel_launch(void* const* d_in, const int* in_sizes, int n_in,
                              void* d_out, int out_size) {
    const float* x    = (const float*)d_in[0];
    const int*   knn  = (const int*)  d_in[1];
    const float* w_e1 = (const float*)d_in[2];
    const float* b_e1 = (const float*)d_in[3];
    const float* w_g1 = (const float*)d_in[4];
    const float* b_g1 = (const float*)d_in[5];
    const float* w_g2 = (const float*)d_in[6];
    const float* b_g2 = (const float*)d_in[7];
    const float* w_e2 = (const float*)d_in[8];
    const float* b_e2 = (const float*)d_in[9];
    const float* w_d1 = (const float*)d_in[10];
    const float* b_d1 = (const float*)d_in[11];
    const float* w_d2 = (const float*)d_in[12];
    const float* b_d2 = (const float*)d_in[13];
    float* out = (float*)d_out;
    const int* src = knn;
    const int* dst = knn + NEDGE;

    __half *p_h0, *p_agg0h, *p_h1, *p_agg1h;
    float *p_lat, *p_lat2, *p_dinv;
    int* p_deg;
    cudaGetSymbolAddress((void**)&p_h0,    g_h0);
    cudaGetSymbolAddress((void**)&p_agg0h, g_agg0h);
    cudaGetSymbolAddress((void**)&p_h1,    g_h1);
    cudaGetSymbolAddress((void**)&p_agg1h, g_agg1h);
    cudaGetSymbolAddress((void**)&p_lat,   g_lat);
    cudaGetSymbolAddress((void**)&p_lat2,  g_lat2);
    cudaGetSymbolAddress((void**)&p_dinv,  g_dinv);
    cudaGetSymbolAddress((void**)&p_deg,   g_deg);

    cudaMemsetAsync(p_deg, 0, BN * sizeof(int));
    cudaMemsetAsync(p_agg0h + ROW0, 0, (size_t)ROW0 * sizeof(__half));
    cudaMemsetAsync(p_agg1h + ROW1, 0, (size_t)ROW1 * sizeof(__half));

    deg_kernel<<<NEDGE / 256, 256>>>(dst);
    cov_e1_kernel<<<BN / 32, 128>>>(x, w_e1, b_e1);

    // GCN layer 1
    edge_kernel<3><<<(NEDGE * 8) / 256, 256>>>(src, dst, p_h0, p_agg0h, ROW0);
    gemm_f16_kernel<C1, C0, false><<<dim3(C1 / 128, BN / 128), 256>>>(
        p_agg0h, ROW0, p_dinv, w_g1, b_g1, p_h1, p_agg1h, nullptr);

    // GCN layer 2 + fused max-pool
    edge_kernel<4><<<(NEDGE * 16) / 256, 256>>>(src, dst, p_h1, p_agg1h, ROW1);
    gemm_f16_kernel<C2, C1, true><<<dim3(C2 / 128, BN / 128), 256>>>(
        p_agg1h, ROW1, p_dinv, w_g2, b_g2, nullptr, nullptr, p_lat);

    e2_kernel<<<dim3(C2 / 128, NB), 128>>>(p_lat, w_e2, b_e2, p_lat2);
    final_kernel<<<BN / 256, 256>>>(p_lat2, w_d1, b_d1, w_d2, b_d2, out);
}